// round 3
// baseline (speedup 1.0000x reference)
#include <cuda_runtime.h>
#include <math.h>

#define B 2
#define S 3072
#define C 1536
#define NH 12
#define HD 128
#define BS (B*S)

// Scratch (allocation-free rule: device globals)
__device__ float g_q[BS*C];
__device__ float g_k[BS*C];
__device__ float g_v[BS*C];
__device__ float g_o[BS*C];

// ---------------------------------------------------------------------------
// SGEMM: Cout[m][n] = sum_k A[m][k] * W[n][k] + bias[n]
// BM=BN=128, BK=16, 256 threads, 8x8 micro-tile per thread.
// Fragment columns split as {tx*4..+3} and {64+tx*4..+3} -> conflict-free LDS.128
// ---------------------------------------------------------------------------
__global__ __launch_bounds__(256) void sgemm_bt_bias(
    const float* __restrict__ A, const float* __restrict__ W,
    const float* __restrict__ bias, float* __restrict__ Cout,
    int M, int N, int K)
{
    __shared__ float As[16][128];
    __shared__ float Bs[16][128];
    int tid = threadIdx.x;
    int bm = blockIdx.y * 128, bn = blockIdx.x * 128;
    int lr = tid >> 2, lc = tid & 3;     // load: row 0..63 (+64), float4 group 0..3
    int tx = tid & 15, ty = tid >> 4;    // compute: 16x16 thread grid

    const float* Ap = A + (size_t)(bm + lr) * K;
    const float* Wp = W + (size_t)(bn + lr) * K;

    float acc[8][8] = {};

    for (int k0 = 0; k0 < K; k0 += 16) {
        float4 a0 = *(const float4*)(Ap + k0 + lc*4);
        float4 a1 = *(const float4*)(Ap + (size_t)64*K + k0 + lc*4);
        float4 w0 = *(const float4*)(Wp + k0 + lc*4);
        float4 w1 = *(const float4*)(Wp + (size_t)64*K + k0 + lc*4);
        __syncthreads();
        As[lc*4+0][lr] = a0.x; As[lc*4+1][lr] = a0.y;
        As[lc*4+2][lr] = a0.z; As[lc*4+3][lr] = a0.w;
        As[lc*4+0][lr+64] = a1.x; As[lc*4+1][lr+64] = a1.y;
        As[lc*4+2][lr+64] = a1.z; As[lc*4+3][lr+64] = a1.w;
        Bs[lc*4+0][lr] = w0.x; Bs[lc*4+1][lr] = w0.y;
        Bs[lc*4+2][lr] = w0.z; Bs[lc*4+3][lr] = w0.w;
        Bs[lc*4+0][lr+64] = w1.x; Bs[lc*4+1][lr+64] = w1.y;
        Bs[lc*4+2][lr+64] = w1.z; Bs[lc*4+3][lr+64] = w1.w;
        __syncthreads();
        #pragma unroll
        for (int kk = 0; kk < 16; kk++) {
            float4 q0 = *(float4*)&As[kk][ty*8];
            float4 q1 = *(float4*)&As[kk][ty*8+4];
            float4 r0 = *(float4*)&Bs[kk][tx*4];
            float4 r1 = *(float4*)&Bs[kk][64 + tx*4];
            float am[8] = {q0.x,q0.y,q0.z,q0.w,q1.x,q1.y,q1.z,q1.w};
            float bv[8] = {r0.x,r0.y,r0.z,r0.w,r1.x,r1.y,r1.z,r1.w};
            #pragma unroll
            for (int i = 0; i < 8; i++)
                #pragma unroll
                for (int j = 0; j < 8; j++)
                    acc[i][j] = fmaf(am[i], bv[j], acc[i][j]);
        }
    }

    float4 b0 = *(const float4*)(bias + bn + tx*4);
    float4 b1 = *(const float4*)(bias + bn + 64 + tx*4);
    #pragma unroll
    for (int i = 0; i < 8; i++) {
        size_t m = (size_t)(bm + ty*8 + i);
        float4 o0 = make_float4(acc[i][0]+b0.x, acc[i][1]+b0.y,
                                acc[i][2]+b0.z, acc[i][3]+b0.w);
        float4 o1 = make_float4(acc[i][4]+b1.x, acc[i][5]+b1.y,
                                acc[i][6]+b1.z, acc[i][7]+b1.w);
        *(float4*)&Cout[m*N + bn + tx*4] = o0;
        *(float4*)&Cout[m*N + bn + 64 + tx*4] = o1;
    }
}

// ---------------------------------------------------------------------------
// Fused RMSNorm (over C) + RoPE (per-head pairs), in-place.
// One block per (b,s) row, 256 threads, float2 pair-granular.
// ang[s][j] = freqs[sel][j], sel = f (j<22) | h (j<43) | w (j<64)
// ---------------------------------------------------------------------------
__global__ __launch_bounds__(256) void rmsnorm_rope(
    float* __restrict__ t, const float* __restrict__ nw,
    const float* __restrict__ freqs)
{
    int bs = blockIdx.x;
    int s = bs % S;
    int tid = threadIdx.x;
    float2* row = (float2*)(t + (size_t)bs * C);
    const float2* wr = (const float2*)nw;

    float2 pv[3], pw[3];
    float ss = 0.f;
    #pragma unroll
    for (int i = 0; i < 3; i++) {
        pv[i] = row[tid + i*256];
        pw[i] = wr[tid + i*256];
        ss += pv[i].x*pv[i].x + pv[i].y*pv[i].y;
    }
    #pragma unroll
    for (int off = 16; off; off >>= 1)
        ss += __shfl_xor_sync(0xffffffffu, ss, off);

    __shared__ float red[8];
    __shared__ float cs[64], sn[64];
    if ((tid & 31) == 0) red[tid >> 5] = ss;
    __syncthreads();
    if (tid < 32) {
        float tsum = (tid < 8) ? red[tid] : 0.f;
        #pragma unroll
        for (int off = 4; off; off >>= 1)
            tsum += __shfl_xor_sync(0xffffffffu, tsum, off);
        if (tid == 0) red[0] = tsum;
    }
    if (tid >= 64 && tid < 128) {
        int j = tid - 64;
        int f = s / 768, r = s % 768, h = r / 32, w = r % 32;
        int sel = (j < 22) ? f : ((j < 43) ? h : w);
        float ang = freqs[sel*64 + j];
        cs[j] = cosf(ang);
        sn[j] = sinf(ang);
    }
    __syncthreads();

    float scale = rsqrtf(red[0] * (1.0f / C) + 1e-6f);
    #pragma unroll
    for (int i = 0; i < 3; i++) {
        int p = tid + i*256;
        int ci = p & 63;
        float e = pv[i].x * scale * pw[i].x;
        float o = pv[i].y * scale * pw[i].y;
        float2 ro;
        ro.x = e*cs[ci] - o*sn[ci];
        ro.y = e*sn[ci] + o*cs[ci];
        row[tid + i*256] = ro;
    }
}

// ---------------------------------------------------------------------------
// fp32 flash attention: BM=64 queries, BN=64 keys, d=128, online softmax.
// Grid (S/64, NH, B), 256 threads. Q/K stored transposed in smem (k-major)
// so fragment loads are conflict-free LDS.128. P staged via smem for PV.
// ---------------------------------------------------------------------------
__global__ __launch_bounds__(256) void flash_attn(
    const float* __restrict__ q, const float* __restrict__ k,
    const float* __restrict__ v, const int* __restrict__ seq_lens,
    float* __restrict__ out)
{
    extern __shared__ float sm[];
    float* QsT = sm;            // [128][64]
    float* KsT = sm + 8192;     // [128][64]
    float* Vs  = sm + 16384;    // [64][128]
    float* Ps  = sm + 24576;    // [64][64]

    int qt = blockIdx.x, head = blockIdx.y, b = blockIdx.z;
    int tid = threadIdx.x;
    int tx = tid & 15, ty = tid >> 4;
    int lr = tid >> 2, lc = tid & 3;
    int seqlen = seq_lens[b];
    const float SC = 0.08838834764831845f;  // 1/sqrt(128)

    const float* qb = q + ((size_t)(b*S + qt*64 + lr))*C + head*HD;
    #pragma unroll
    for (int i = 0; i < 8; i++) {
        int dd = lc*32 + i*4;
        float4 t = *(const float4*)(qb + dd);
        QsT[(dd+0)*64 + lr] = t.x * SC;
        QsT[(dd+1)*64 + lr] = t.y * SC;
        QsT[(dd+2)*64 + lr] = t.z * SC;
        QsT[(dd+3)*64 + lr] = t.w * SC;
    }

    float m_i[4], l_i[4], acc[4][8];
    #pragma unroll
    for (int i = 0; i < 4; i++) {
        m_i[i] = -1e30f; l_i[i] = 0.f;
        #pragma unroll
        for (int j = 0; j < 8; j++) acc[i][j] = 0.f;
    }

    int ntiles = (seqlen + 63) >> 6;
    const float* kb = k + ((size_t)b*S + lr)*C + head*HD;
    const float* vb = v + ((size_t)b*S + lr)*C + head*HD;

    for (int kt = 0; kt < ntiles; kt++) {
        __syncthreads();
        size_t off = (size_t)kt * 64 * C;
        #pragma unroll
        for (int i = 0; i < 8; i++) {
            int dd = lc*32 + i*4;
            float4 t = *(const float4*)(kb + off + dd);
            KsT[(dd+0)*64 + lr] = t.x; KsT[(dd+1)*64 + lr] = t.y;
            KsT[(dd+2)*64 + lr] = t.z; KsT[(dd+3)*64 + lr] = t.w;
            float4 u = *(const float4*)(vb + off + dd);
            *(float4*)&Vs[lr*128 + dd] = u;
        }
        __syncthreads();

        // S = Q Kᵀ (already scaled)
        float sc[4][4] = {};
        #pragma unroll 8
        for (int kk = 0; kk < 128; kk++) {
            float4 qq = *(float4*)&QsT[kk*64 + ty*4];
            float4 kv = *(float4*)&KsT[kk*64 + tx*4];
            float qr[4] = {qq.x,qq.y,qq.z,qq.w};
            float kr[4] = {kv.x,kv.y,kv.z,kv.w};
            #pragma unroll
            for (int i = 0; i < 4; i++)
                #pragma unroll
                for (int j = 0; j < 4; j++)
                    sc[i][j] = fmaf(qr[i], kr[j], sc[i][j]);
        }

        // mask
        int kbase = kt*64 + tx*4;
        #pragma unroll
        for (int j = 0; j < 4; j++) {
            if (kbase + j >= seqlen) {
                #pragma unroll
                for (int i = 0; i < 4; i++) sc[i][j] = -1e30f;
            }
        }

        // online softmax (rows split across the 16 tx lanes of a half-warp)
        #pragma unroll
        for (int i = 0; i < 4; i++) {
            float rm = fmaxf(fmaxf(sc[i][0], sc[i][1]), fmaxf(sc[i][2], sc[i][3]));
            rm = fmaxf(rm, __shfl_xor_sync(0xffffffffu, rm, 1));
            rm = fmaxf(rm, __shfl_xor_sync(0xffffffffu, rm, 2));
            rm = fmaxf(rm, __shfl_xor_sync(0xffffffffu, rm, 4));
            rm = fmaxf(rm, __shfl_xor_sync(0xffffffffu, rm, 8));
            float mnew = fmaxf(m_i[i], rm);
            float alpha = __expf(m_i[i] - mnew);
            float psum = 0.f;
            #pragma unroll
            for (int j = 0; j < 4; j++) {
                float pj = __expf(sc[i][j] - mnew);
                psum += pj;
                sc[i][j] = pj;
            }
            psum += __shfl_xor_sync(0xffffffffu, psum, 1);
            psum += __shfl_xor_sync(0xffffffffu, psum, 2);
            psum += __shfl_xor_sync(0xffffffffu, psum, 4);
            psum += __shfl_xor_sync(0xffffffffu, psum, 8);
            l_i[i] = l_i[i] * alpha + psum;
            m_i[i] = mnew;
            #pragma unroll
            for (int jj = 0; jj < 8; jj++) acc[i][jj] *= alpha;
            *(float4*)&Ps[(ty*4+i)*64 + tx*4] =
                make_float4(sc[i][0], sc[i][1], sc[i][2], sc[i][3]);
        }
        __syncthreads();

        // O += P V
        #pragma unroll 4
        for (int kk = 0; kk < 64; kk++) {
            float4 v0 = *(float4*)&Vs[kk*128 + tx*4];
            float4 v1 = *(float4*)&Vs[kk*128 + 64 + tx*4];
            float pr[4];
            #pragma unroll
            for (int i = 0; i < 4; i++) pr[i] = Ps[(ty*4+i)*64 + kk];
            #pragma unroll
            for (int i = 0; i < 4; i++) {
                acc[i][0] = fmaf(pr[i], v0.x, acc[i][0]);
                acc[i][1] = fmaf(pr[i], v0.y, acc[i][1]);
                acc[i][2] = fmaf(pr[i], v0.z, acc[i][2]);
                acc[i][3] = fmaf(pr[i], v0.w, acc[i][3]);
                acc[i][4] = fmaf(pr[i], v1.x, acc[i][4]);
                acc[i][5] = fmaf(pr[i], v1.y, acc[i][5]);
                acc[i][6] = fmaf(pr[i], v1.z, acc[i][6]);
                acc[i][7] = fmaf(pr[i], v1.w, acc[i][7]);
            }
        }
    }

    float* ob = out + ((size_t)(b*S + qt*64 + ty*4))*C + head*HD;
    #pragma unroll
    for (int i = 0; i < 4; i++) {
        float inv = 1.0f / l_i[i];
        float4 o0 = make_float4(acc[i][0]*inv, acc[i][1]*inv,
                                acc[i][2]*inv, acc[i][3]*inv);
        float4 o1 = make_float4(acc[i][4]*inv, acc[i][5]*inv,
                                acc[i][6]*inv, acc[i][7]*inv);
        *(float4*)(ob + (size_t)i*C + tx*4) = o0;
        *(float4*)(ob + (size_t)i*C + 64 + tx*4) = o1;
    }
}

// ---------------------------------------------------------------------------
extern "C" void kernel_launch(void* const* d_in, const int* in_sizes, int n_in,
                              void* d_out, int out_size)
{
    const float* x     = (const float*)d_in[0];
    const int*   seq   = (const int*)  d_in[1];
    // d_in[2] = grid_sizes (compile-time constant here)
    const float* freqs = (const float*)d_in[3];
    const float* Wq    = (const float*)d_in[4];
    const float* bq    = (const float*)d_in[5];
    const float* Wk    = (const float*)d_in[6];
    const float* bk    = (const float*)d_in[7];
    const float* Wv    = (const float*)d_in[8];
    const float* bv    = (const float*)d_in[9];
    const float* Wo    = (const float*)d_in[10];
    const float* bo    = (const float*)d_in[11];
    const float* nqw   = (const float*)d_in[12];
    const float* nkw   = (const float*)d_in[13];
    float* out = (float*)d_out;

    float *pq, *pk, *pv, *po;
    cudaGetSymbolAddress((void**)&pq, g_q);
    cudaGetSymbolAddress((void**)&pk, g_k);
    cudaGetSymbolAddress((void**)&pv, g_v);
    cudaGetSymbolAddress((void**)&po, g_o);

    dim3 gg(C/128, BS/128);
    sgemm_bt_bias<<<gg, 256>>>(x, Wq, bq, pq, BS, C, C);
    sgemm_bt_bias<<<gg, 256>>>(x, Wk, bk, pk, BS, C, C);
    sgemm_bt_bias<<<gg, 256>>>(x, Wv, bv, pv, BS, C, C);
    rmsnorm_rope<<<BS, 256>>>(pq, nqw, freqs);
    rmsnorm_rope<<<BS, 256>>>(pk, nkw, freqs);

    static bool attr_set = false;
    // cudaFuncSetAttribute is not stream-ordered; safe under graph capture.
    cudaFuncSetAttribute(flash_attn,
                         cudaFuncAttributeMaxDynamicSharedMemorySize, 114688);
    (void)attr_set;
    flash_attn<<<dim3(S/64, NH, B), 256, 114688>>>(pq, pk, pv, seq, po);

    sgemm_bt_bias<<<gg, 256>>>(po, Wo, bo, out, BS, C, C);
}

// round 4
// speedup vs baseline: 3.2583x; 3.2583x over previous
#include <cuda_runtime.h>
#include <math.h>

#define B 2
#define S 3072
#define C 1536
#define NH 12
#define HD 128
#define BS (B*S)

// Scratch (allocation-free rule: device globals)
__device__ float g_q[BS*C];
__device__ float g_k[BS*C];
__device__ float g_v[BS*C];
__device__ float g_o[BS*C];

// ---------------------------------------------------------------------------
// tf32 helpers
// ---------------------------------------------------------------------------
__device__ __forceinline__ float tf32f(float x) {
    unsigned r;
    asm("cvt.rna.tf32.f32 %0, %1;" : "=r"(r) : "f"(x));
    return __uint_as_float(r);
}

__device__ __forceinline__ void mma_tf32(float* d,
    unsigned a0, unsigned a1, unsigned a2, unsigned a3,
    unsigned b0, unsigned b1)
{
    asm volatile(
        "mma.sync.aligned.m16n8k8.row.col.f32.tf32.tf32.f32 "
        "{%0,%1,%2,%3}, {%4,%5,%6,%7}, {%8,%9}, {%0,%1,%2,%3};\n"
        : "+f"(d[0]), "+f"(d[1]), "+f"(d[2]), "+f"(d[3])
        : "r"(a0), "r"(a1), "r"(a2), "r"(a3), "r"(b0), "r"(b1));
}

// ---------------------------------------------------------------------------
// tf32 SGEMM: Cout[m][n] = sum_k A[m][k]*W[n][k] + bias[n]
// 128x128x16 tile, 256 threads = 8 warps, warp tile 32x64 (m16n8k8).
// Smem row-major stride 20 -> fragment LDS bank pattern (20*gr+gc) conflict-free
// ---------------------------------------------------------------------------
#define GS 20   // smem row stride (16 + 4 pad)

__global__ __launch_bounds__(256) void sgemm_tf32(
    const float* __restrict__ A, const float* __restrict__ W,
    const float* __restrict__ bias, float* __restrict__ Cout,
    int M, int N, int K)
{
    __shared__ float As[128*GS];
    __shared__ float Bs[128*GS];
    int tid  = threadIdx.x;
    int bm   = blockIdx.y*128, bn = blockIdx.x*128;
    int lr   = tid >> 2, lc = tid & 3;     // staging: row, float4 group
    int wid  = tid >> 5, lane = tid & 31;
    int wm   = wid & 3, wn = wid >> 2;     // warp 32-row / 64-col stripes
    int gr   = lane >> 2, gc = lane & 3;

    const float* Ap = A + (size_t)(bm + lr) * K;
    const float* Wp = W + (size_t)(bn + lr) * K;

    float acc[2][8][4];
    #pragma unroll
    for (int mt = 0; mt < 2; mt++)
        #pragma unroll
        for (int nt = 0; nt < 8; nt++)
            #pragma unroll
            for (int j = 0; j < 4; j++) acc[mt][nt][j] = 0.f;

    for (int k0 = 0; k0 < K; k0 += 16) {
        float4 a0 = *(const float4*)(Ap + k0 + lc*4);
        float4 a1 = *(const float4*)(Ap + (size_t)64*K + k0 + lc*4);
        float4 w0 = *(const float4*)(Wp + k0 + lc*4);
        float4 w1 = *(const float4*)(Wp + (size_t)64*K + k0 + lc*4);
        __syncthreads();
        *(float4*)&As[lr*GS + lc*4] =
            make_float4(tf32f(a0.x), tf32f(a0.y), tf32f(a0.z), tf32f(a0.w));
        *(float4*)&As[(lr+64)*GS + lc*4] =
            make_float4(tf32f(a1.x), tf32f(a1.y), tf32f(a1.z), tf32f(a1.w));
        *(float4*)&Bs[lr*GS + lc*4] =
            make_float4(tf32f(w0.x), tf32f(w0.y), tf32f(w0.z), tf32f(w0.w));
        *(float4*)&Bs[(lr+64)*GS + lc*4] =
            make_float4(tf32f(w1.x), tf32f(w1.y), tf32f(w1.z), tf32f(w1.w));
        __syncthreads();

        #pragma unroll
        for (int ks = 0; ks < 2; ks++) {
            unsigned af[2][4];
            #pragma unroll
            for (int mt = 0; mt < 2; mt++) {
                int r = wm*32 + mt*16;
                af[mt][0] = __float_as_uint(As[(r+gr  )*GS + ks*8 + gc    ]);
                af[mt][1] = __float_as_uint(As[(r+gr+8)*GS + ks*8 + gc    ]);
                af[mt][2] = __float_as_uint(As[(r+gr  )*GS + ks*8 + gc + 4]);
                af[mt][3] = __float_as_uint(As[(r+gr+8)*GS + ks*8 + gc + 4]);
            }
            #pragma unroll
            for (int nt = 0; nt < 8; nt++) {
                int nrow = wn*64 + nt*8 + gr;
                unsigned b0 = __float_as_uint(Bs[nrow*GS + ks*8 + gc    ]);
                unsigned b1 = __float_as_uint(Bs[nrow*GS + ks*8 + gc + 4]);
                mma_tf32(acc[0][nt], af[0][0], af[0][1], af[0][2], af[0][3], b0, b1);
                mma_tf32(acc[1][nt], af[1][0], af[1][1], af[1][2], af[1][3], b0, b1);
            }
        }
    }

    #pragma unroll
    for (int mt = 0; mt < 2; mt++) {
        int r0 = bm + wm*32 + mt*16 + gr;
        #pragma unroll
        for (int nt = 0; nt < 8; nt++) {
            int col = bn + wn*64 + nt*8 + 2*gc;
            float2 bb = *(const float2*)(bias + col);
            float2 o0 = make_float2(acc[mt][nt][0] + bb.x, acc[mt][nt][1] + bb.y);
            float2 o1 = make_float2(acc[mt][nt][2] + bb.x, acc[mt][nt][3] + bb.y);
            *(float2*)&Cout[(size_t)r0*N + col]     = o0;
            *(float2*)&Cout[(size_t)(r0+8)*N + col] = o1;
        }
    }
}

// ---------------------------------------------------------------------------
// Fused RMSNorm + RoPE (unchanged from passing version)
// ---------------------------------------------------------------------------
__global__ __launch_bounds__(256) void rmsnorm_rope(
    float* __restrict__ t, const float* __restrict__ nw,
    const float* __restrict__ freqs)
{
    int bs = blockIdx.x;
    int s = bs % S;
    int tid = threadIdx.x;
    float2* row = (float2*)(t + (size_t)bs * C);
    const float2* wr = (const float2*)nw;

    float2 pv[3], pw[3];
    float ss = 0.f;
    #pragma unroll
    for (int i = 0; i < 3; i++) {
        pv[i] = row[tid + i*256];
        pw[i] = wr[tid + i*256];
        ss += pv[i].x*pv[i].x + pv[i].y*pv[i].y;
    }
    #pragma unroll
    for (int off = 16; off; off >>= 1)
        ss += __shfl_xor_sync(0xffffffffu, ss, off);

    __shared__ float red[8];
    __shared__ float cs[64], sn[64];
    if ((tid & 31) == 0) red[tid >> 5] = ss;
    __syncthreads();
    if (tid < 32) {
        float tsum = (tid < 8) ? red[tid] : 0.f;
        #pragma unroll
        for (int off = 4; off; off >>= 1)
            tsum += __shfl_xor_sync(0xffffffffu, tsum, off);
        if (tid == 0) red[0] = tsum;
    }
    if (tid >= 64 && tid < 128) {
        int j = tid - 64;
        int f = s / 768, r = s % 768, h = r / 32, w = r % 32;
        int sel = (j < 22) ? f : ((j < 43) ? h : w);
        float ang = freqs[sel*64 + j];
        cs[j] = cosf(ang);
        sn[j] = sinf(ang);
    }
    __syncthreads();

    float scale = rsqrtf(red[0] * (1.0f / C) + 1e-6f);
    #pragma unroll
    for (int i = 0; i < 3; i++) {
        int p = tid + i*256;
        int ci = p & 63;
        float e = pv[i].x * scale * pw[i].x;
        float o = pv[i].y * scale * pw[i].y;
        float2 ro;
        ro.x = e*cs[ci] - o*sn[ci];
        ro.y = e*sn[ci] + o*cs[ci];
        row[tid + i*256] = ro;
    }
}

// ---------------------------------------------------------------------------
// tf32 flash attention: BM=128 queries, BN=64 keys, d=128.
// 8 warps, each owns a 16-row stripe (softmax fully warp-local).
// Qs[128][132], Ks[64][132], Vs[64][136], Ps[128][68] — fragment loads verified
// conflict-free: (132*gr+gc)%32, (68*gr+gc)%32, (136*gc+gr)%32 all distinct.
// ---------------------------------------------------------------------------
#define QS_ST 132
#define KS_ST 132
#define VS_ST 136
#define PS_ST 68
#define FA_SMEM ((128*QS_ST + 64*KS_ST + 64*VS_ST + 128*PS_ST) * 4)

__global__ __launch_bounds__(256) void flash_tf32(
    const float* __restrict__ q, const float* __restrict__ k,
    const float* __restrict__ v, const int* __restrict__ seq_lens,
    float* __restrict__ out)
{
    extern __shared__ float sm[];
    float* Qs = sm;                        // [128][132]
    float* Ks = Qs + 128*QS_ST;            // [64][132]
    float* Vs = Ks + 64*KS_ST;             // [64][136]
    float* Ps = Vs + 64*VS_ST;             // [128][68]

    int qt = blockIdx.x, head = blockIdx.y, b = blockIdx.z;
    int tid = threadIdx.x;
    int wid = tid >> 5, lane = tid & 31;
    int gr = lane >> 2, gc = lane & 3;
    int qrow = wid * 16;
    int seqlen = seq_lens[b];
    const float SC = 0.08838834764831845f;  // 1/sqrt(128)

    // Stage Q (scaled + tf32). Each warp stages full rows -> coalesced.
    const float* qb = q + ((size_t)(b*S + qt*128))*C + head*HD;
    #pragma unroll
    for (int i = 0; i < 16; i++) {
        int idx = tid + i*256;
        int row = idx >> 5, c4 = idx & 31;
        float4 t = *(const float4*)(qb + (size_t)row*C + c4*4);
        *(float4*)&Qs[row*QS_ST + c4*4] =
            make_float4(tf32f(t.x*SC), tf32f(t.y*SC), tf32f(t.z*SC), tf32f(t.w*SC));
    }

    float oacc[16][4];
    #pragma unroll
    for (int nt = 0; nt < 16; nt++)
        #pragma unroll
        for (int j = 0; j < 4; j++) oacc[nt][j] = 0.f;
    float m0 = -1e30f, m1 = -1e30f, l0 = 0.f, l1 = 0.f;

    int ntiles = (seqlen + 63) >> 6;
    const float* kb = k + ((size_t)(b*S))*C + head*HD;
    const float* vb = v + ((size_t)(b*S))*C + head*HD;

    for (int kt = 0; kt < ntiles; kt++) {
        __syncthreads();
        #pragma unroll
        for (int i = 0; i < 8; i++) {
            int idx = tid + i*256;
            int row = idx >> 5, c4 = idx & 31;
            size_t goff = (size_t)(kt*64 + row)*C + c4*4;
            float4 t = *(const float4*)(kb + goff);
            *(float4*)&Ks[row*KS_ST + c4*4] =
                make_float4(tf32f(t.x), tf32f(t.y), tf32f(t.z), tf32f(t.w));
            float4 u = *(const float4*)(vb + goff);
            *(float4*)&Vs[row*VS_ST + c4*4] =
                make_float4(tf32f(u.x), tf32f(u.y), tf32f(u.z), tf32f(u.w));
        }
        __syncthreads();

        // S = Q K^T  (scale folded into Q)
        float sacc[8][4];
        #pragma unroll
        for (int nt = 0; nt < 8; nt++)
            #pragma unroll
            for (int j = 0; j < 4; j++) sacc[nt][j] = 0.f;

        #pragma unroll
        for (int ks = 0; ks < 16; ks++) {
            unsigned a0 = __float_as_uint(Qs[(qrow+gr  )*QS_ST + ks*8 + gc    ]);
            unsigned a1 = __float_as_uint(Qs[(qrow+gr+8)*QS_ST + ks*8 + gc    ]);
            unsigned a2 = __float_as_uint(Qs[(qrow+gr  )*QS_ST + ks*8 + gc + 4]);
            unsigned a3 = __float_as_uint(Qs[(qrow+gr+8)*QS_ST + ks*8 + gc + 4]);
            #pragma unroll
            for (int nt = 0; nt < 8; nt++) {
                unsigned b0 = __float_as_uint(Ks[(nt*8+gr)*KS_ST + ks*8 + gc    ]);
                unsigned b1 = __float_as_uint(Ks[(nt*8+gr)*KS_ST + ks*8 + gc + 4]);
                mma_tf32(sacc[nt], a0, a1, a2, a3, b0, b1);
            }
        }

        // mask (only last partial tile)
        if (kt*64 + 64 > seqlen) {
            #pragma unroll
            for (int nt = 0; nt < 8; nt++) {
                int c0 = kt*64 + nt*8 + 2*gc;
                if (c0     >= seqlen) { sacc[nt][0] = -1e30f; sacc[nt][2] = -1e30f; }
                if (c0 + 1 >= seqlen) { sacc[nt][1] = -1e30f; sacc[nt][3] = -1e30f; }
            }
        }

        // online softmax — rows gr (regs 0,1) and gr+8 (regs 2,3), reduce
        // across the 4 lanes sharing a row (xor 1, xor 2)
        float rm0 = -1e30f, rm1 = -1e30f;
        #pragma unroll
        for (int nt = 0; nt < 8; nt++) {
            rm0 = fmaxf(rm0, fmaxf(sacc[nt][0], sacc[nt][1]));
            rm1 = fmaxf(rm1, fmaxf(sacc[nt][2], sacc[nt][3]));
        }
        rm0 = fmaxf(rm0, __shfl_xor_sync(0xffffffffu, rm0, 1));
        rm0 = fmaxf(rm0, __shfl_xor_sync(0xffffffffu, rm0, 2));
        rm1 = fmaxf(rm1, __shfl_xor_sync(0xffffffffu, rm1, 1));
        rm1 = fmaxf(rm1, __shfl_xor_sync(0xffffffffu, rm1, 2));
        float mn0 = fmaxf(m0, rm0), mn1 = fmaxf(m1, rm1);
        float al0 = __expf(m0 - mn0), al1 = __expf(m1 - mn1);
        #pragma unroll
        for (int nt = 0; nt < 16; nt++) {
            oacc[nt][0] *= al0; oacc[nt][1] *= al0;
            oacc[nt][2] *= al1; oacc[nt][3] *= al1;
        }
        float ps0 = 0.f, ps1 = 0.f;
        #pragma unroll
        for (int nt = 0; nt < 8; nt++) {
            int col = nt*8 + 2*gc;
            float p0 = __expf(sacc[nt][0] - mn0);
            float p1 = __expf(sacc[nt][1] - mn0);
            float p2 = __expf(sacc[nt][2] - mn1);
            float p3 = __expf(sacc[nt][3] - mn1);
            ps0 += p0 + p1;
            ps1 += p2 + p3;
            Ps[(qrow+gr  )*PS_ST + col    ] = tf32f(p0);
            Ps[(qrow+gr  )*PS_ST + col + 1] = tf32f(p1);
            Ps[(qrow+gr+8)*PS_ST + col    ] = tf32f(p2);
            Ps[(qrow+gr+8)*PS_ST + col + 1] = tf32f(p3);
        }
        ps0 += __shfl_xor_sync(0xffffffffu, ps0, 1);
        ps0 += __shfl_xor_sync(0xffffffffu, ps0, 2);
        ps1 += __shfl_xor_sync(0xffffffffu, ps1, 1);
        ps1 += __shfl_xor_sync(0xffffffffu, ps1, 2);
        l0 = l0*al0 + ps0; m0 = mn0;
        l1 = l1*al1 + ps1; m1 = mn1;
        __syncwarp();

        // O += P V
        #pragma unroll
        for (int ks2 = 0; ks2 < 8; ks2++) {
            unsigned a0 = __float_as_uint(Ps[(qrow+gr  )*PS_ST + ks2*8 + gc    ]);
            unsigned a1 = __float_as_uint(Ps[(qrow+gr+8)*PS_ST + ks2*8 + gc    ]);
            unsigned a2 = __float_as_uint(Ps[(qrow+gr  )*PS_ST + ks2*8 + gc + 4]);
            unsigned a3 = __float_as_uint(Ps[(qrow+gr+8)*PS_ST + ks2*8 + gc + 4]);
            #pragma unroll
            for (int nt2 = 0; nt2 < 16; nt2++) {
                unsigned b0 = __float_as_uint(Vs[(ks2*8+gc  )*VS_ST + nt2*8 + gr]);
                unsigned b1 = __float_as_uint(Vs[(ks2*8+gc+4)*VS_ST + nt2*8 + gr]);
                mma_tf32(oacc[nt2], a0, a1, a2, a3, b0, b1);
            }
        }
        __syncwarp();
    }

    float inv0 = 1.0f / l0, inv1 = 1.0f / l1;
    float* ob = out + ((size_t)(b*S + qt*128 + qrow + gr))*C + head*HD;
    #pragma unroll
    for (int nt2 = 0; nt2 < 16; nt2++) {
        int col = nt2*8 + 2*gc;
        *(float2*)(ob + col) =
            make_float2(oacc[nt2][0]*inv0, oacc[nt2][1]*inv0);
        *(float2*)(ob + (size_t)8*C + col) =
            make_float2(oacc[nt2][2]*inv1, oacc[nt2][3]*inv1);
    }
}

// ---------------------------------------------------------------------------
extern "C" void kernel_launch(void* const* d_in, const int* in_sizes, int n_in,
                              void* d_out, int out_size)
{
    const float* x     = (const float*)d_in[0];
    const int*   seq   = (const int*)  d_in[1];
    // d_in[2] = grid_sizes (compile-time constant here)
    const float* freqs = (const float*)d_in[3];
    const float* Wq    = (const float*)d_in[4];
    const float* bq    = (const float*)d_in[5];
    const float* Wk    = (const float*)d_in[6];
    const float* bk    = (const float*)d_in[7];
    const float* Wv    = (const float*)d_in[8];
    const float* bv    = (const float*)d_in[9];
    const float* Wo    = (const float*)d_in[10];
    const float* bo    = (const float*)d_in[11];
    const float* nqw   = (const float*)d_in[12];
    const float* nkw   = (const float*)d_in[13];
    float* out = (float*)d_out;

    float *pq, *pk, *pv, *po;
    cudaGetSymbolAddress((void**)&pq, g_q);
    cudaGetSymbolAddress((void**)&pk, g_k);
    cudaGetSymbolAddress((void**)&pv, g_v);
    cudaGetSymbolAddress((void**)&po, g_o);

    dim3 gg(C/128, BS/128);
    sgemm_tf32<<<gg, 256>>>(x, Wq, bq, pq, BS, C, C);
    sgemm_tf32<<<gg, 256>>>(x, Wk, bk, pk, BS, C, C);
    sgemm_tf32<<<gg, 256>>>(x, Wv, bv, pv, BS, C, C);
    rmsnorm_rope<<<BS, 256>>>(pq, nqw, freqs);
    rmsnorm_rope<<<BS, 256>>>(pk, nkw, freqs);

    cudaFuncSetAttribute(flash_tf32,
                         cudaFuncAttributeMaxDynamicSharedMemorySize, FA_SMEM);
    flash_tf32<<<dim3(S/128, NH, B), 256, FA_SMEM>>>(pq, pk, pv, seq, po);

    sgemm_tf32<<<gg, 256>>>(po, Wo, bo, out, BS, C, C);
}

// round 9
// speedup vs baseline: 5.1302x; 1.5745x over previous
#include <cuda_runtime.h>
#include <cuda_fp16.h>
#include <math.h>
#include <stdint.h>

#define B 2
#define S 3072
#define C 1536
#define NH 12
#define HD 128
#define BS (B*S)

// Scratch (allocation-free rule: device globals)
__device__ float g_q[BS*C];
__device__ float g_k[BS*C];
__device__ float g_v[BS*C];
__device__ float g_o[BS*C];

// ---------------------------------------------------------------------------
// helpers
// ---------------------------------------------------------------------------
__device__ __forceinline__ unsigned packh2(float x, float y) {
    __half2 h = __floats2half2_rn(x, y);
    return *reinterpret_cast<unsigned*>(&h);
}

// fp16 mma, fp32 accumulate: D(16x8) += A(16x16) * B(16x8)
__device__ __forceinline__ void mma_f16(float* d,
    unsigned a0, unsigned a1, unsigned a2, unsigned a3,
    unsigned b0, unsigned b1)
{
    asm volatile(
        "mma.sync.aligned.m16n8k16.row.col.f32.f16.f16.f32 "
        "{%0,%1,%2,%3}, {%4,%5,%6,%7}, {%8,%9}, {%0,%1,%2,%3};\n"
        : "+f"(d[0]), "+f"(d[1]), "+f"(d[2]), "+f"(d[3])
        : "r"(a0), "r"(a1), "r"(a2), "r"(a3), "r"(b0), "r"(b1));
}

__device__ __forceinline__ void ldmx4t(unsigned& r0, unsigned& r1,
                                       unsigned& r2, unsigned& r3, uint32_t a)
{
    asm volatile(
        "ldmatrix.sync.aligned.m8n8.x4.trans.shared.b16 {%0,%1,%2,%3}, [%4];"
        : "=r"(r0), "=r"(r1), "=r"(r2), "=r"(r3) : "r"(a));
}

// ---------------------------------------------------------------------------
// fp16 GEMM: Cout[m][n] = sum_k A[m][k]*W[n][k] + bias[n]
// 128x128 tile, BK=32 halves, 256 threads = 8 warps, warp tile 32x64.
// Smem: half2 (uint) arrays, row stride 20 uints (16 data + 4 pad).
// Fragment LDS bank pattern (20*gr+gc) mod 32: conflict-free.
// ---------------------------------------------------------------------------
#define GST 20

__global__ __launch_bounds__(256) void sgemm_f16(
    const float* __restrict__ A, const float* __restrict__ W,
    const float* __restrict__ bias, float* __restrict__ Cout,
    int M, int N, int K)
{
    __shared__ unsigned As[128*GST];
    __shared__ unsigned Bs[128*GST];
    int tid  = threadIdx.x;
    int bm   = blockIdx.y*128, bn = blockIdx.x*128;
    int lr   = tid >> 3, lc = tid & 7;     // staging: base row, float4 group (of 8)
    int wid  = tid >> 5, lane = tid & 31;
    int wm   = wid & 3, wn = wid >> 2;
    int gr   = lane >> 2, gc = lane & 3;

    const float* Ap = A + (size_t)(bm + lr) * K;
    const float* Wp = W + (size_t)(bn + lr) * K;

    float acc[2][8][4];
    #pragma unroll
    for (int mt = 0; mt < 2; mt++)
        #pragma unroll
        for (int nt = 0; nt < 8; nt++)
            #pragma unroll
            for (int j = 0; j < 4; j++) acc[mt][nt][j] = 0.f;

    for (int k0 = 0; k0 < K; k0 += 32) {
        float4 av[4], wv[4];
        #pragma unroll
        for (int i = 0; i < 4; i++) {
            av[i] = *(const float4*)(Ap + (size_t)(i*32)*K + k0 + lc*4);
            wv[i] = *(const float4*)(Wp + (size_t)(i*32)*K + k0 + lc*4);
        }
        __syncthreads();
        #pragma unroll
        for (int i = 0; i < 4; i++) {
            int row = lr + i*32;
            *(uint2*)&As[row*GST + lc*2] =
                make_uint2(packh2(av[i].x, av[i].y), packh2(av[i].z, av[i].w));
            *(uint2*)&Bs[row*GST + lc*2] =
                make_uint2(packh2(wv[i].x, wv[i].y), packh2(wv[i].z, wv[i].w));
        }
        __syncthreads();

        #pragma unroll
        for (int ks = 0; ks < 2; ks++) {
            unsigned af[2][4];
            #pragma unroll
            for (int mt = 0; mt < 2; mt++) {
                int r = wm*32 + mt*16;
                af[mt][0] = As[(r+gr  )*GST + ks*8 + gc    ];
                af[mt][1] = As[(r+gr+8)*GST + ks*8 + gc    ];
                af[mt][2] = As[(r+gr  )*GST + ks*8 + gc + 4];
                af[mt][3] = As[(r+gr+8)*GST + ks*8 + gc + 4];
            }
            #pragma unroll
            for (int nt = 0; nt < 8; nt++) {
                int nrow = wn*64 + nt*8 + gr;
                unsigned b0 = Bs[nrow*GST + ks*8 + gc    ];
                unsigned b1 = Bs[nrow*GST + ks*8 + gc + 4];
                mma_f16(acc[0][nt], af[0][0], af[0][1], af[0][2], af[0][3], b0, b1);
                mma_f16(acc[1][nt], af[1][0], af[1][1], af[1][2], af[1][3], b0, b1);
            }
        }
    }

    #pragma unroll
    for (int mt = 0; mt < 2; mt++) {
        int r0 = bm + wm*32 + mt*16 + gr;
        #pragma unroll
        for (int nt = 0; nt < 8; nt++) {
            int col = bn + wn*64 + nt*8 + 2*gc;
            float2 bb = *(const float2*)(bias + col);
            float2 o0 = make_float2(acc[mt][nt][0] + bb.x, acc[mt][nt][1] + bb.y);
            float2 o1 = make_float2(acc[mt][nt][2] + bb.x, acc[mt][nt][3] + bb.y);
            *(float2*)&Cout[(size_t)r0*N + col]     = o0;
            *(float2*)&Cout[(size_t)(r0+8)*N + col] = o1;
        }
    }
}

// ---------------------------------------------------------------------------
// Fused RMSNorm + RoPE (unchanged, proven)
// ---------------------------------------------------------------------------
__global__ __launch_bounds__(256) void rmsnorm_rope(
    float* __restrict__ t, const float* __restrict__ nw,
    const float* __restrict__ freqs)
{
    int bs = blockIdx.x;
    int s = bs % S;
    int tid = threadIdx.x;
    float2* row = (float2*)(t + (size_t)bs * C);
    const float2* wr = (const float2*)nw;

    float2 pv[3], pw[3];
    float ss = 0.f;
    #pragma unroll
    for (int i = 0; i < 3; i++) {
        pv[i] = row[tid + i*256];
        pw[i] = wr[tid + i*256];
        ss += pv[i].x*pv[i].x + pv[i].y*pv[i].y;
    }
    #pragma unroll
    for (int off = 16; off; off >>= 1)
        ss += __shfl_xor_sync(0xffffffffu, ss, off);

    __shared__ float red[8];
    __shared__ float cs[64], sn[64];
    if ((tid & 31) == 0) red[tid >> 5] = ss;
    __syncthreads();
    if (tid < 32) {
        float tsum = (tid < 8) ? red[tid] : 0.f;
        #pragma unroll
        for (int off = 4; off; off >>= 1)
            tsum += __shfl_xor_sync(0xffffffffu, tsum, off);
        if (tid == 0) red[0] = tsum;
    }
    if (tid >= 64 && tid < 128) {
        int j = tid - 64;
        int f = s / 768, r = s % 768, h = r / 32, w = r % 32;
        int sel = (j < 22) ? f : ((j < 43) ? h : w);
        float ang = freqs[sel*64 + j];
        cs[j] = cosf(ang);
        sn[j] = sinf(ang);
    }
    __syncthreads();

    float scale = rsqrtf(red[0] * (1.0f / C) + 1e-6f);
    #pragma unroll
    for (int i = 0; i < 3; i++) {
        int p = tid + i*256;
        int ci = p & 63;
        float e = pv[i].x * scale * pw[i].x;
        float o = pv[i].y * scale * pw[i].y;
        float2 ro;
        ro.x = e*cs[ci] - o*sn[ci];
        ro.y = e*sn[ci] + o*cs[ci];
        row[tid + i*256] = ro;
    }
}

// ---------------------------------------------------------------------------
// fp16 flash attention: BM=128 queries, BN=64 keys, d=128.
// 8 warps, one 16-row stripe each. Smem in half2 (uint) units:
//   Qs[128][68], Ks[64][68], Vs[64][68], Ps[128][36]  (strides inc. pad)
// QK^T/PV via m16n8k16; V B-fragments via ldmatrix.x4.trans (row stride
// 68 uints = 17 x 16B -> conflict-free phases). Softmax fp32.
// ---------------------------------------------------------------------------
#define QK_ST 68
#define PS_ST 36
#define OFF_K (128*QK_ST)
#define OFF_V (OFF_K + 64*QK_ST)
#define OFF_P (OFF_V + 64*QK_ST)
#define FA_SMEM ((OFF_P + 128*PS_ST) * 4)

__global__ __launch_bounds__(256) void flash_f16(
    const float* __restrict__ q, const float* __restrict__ k,
    const float* __restrict__ v, const int* __restrict__ seq_lens,
    float* __restrict__ out)
{
    extern __shared__ unsigned sm[];
    unsigned* Qs = sm;
    unsigned* Ks = sm + OFF_K;
    unsigned* Vs = sm + OFF_V;
    unsigned* Ps = sm + OFF_P;

    int qt = blockIdx.x, head = blockIdx.y, b = blockIdx.z;
    int tid = threadIdx.x;
    int wid = tid >> 5, lane = tid & 31;
    int gr = lane >> 2, gc = lane & 3;
    int qrow = wid * 16;
    int seqlen = seq_lens[b];
    const float SC = 0.08838834764831845f;   // 1/sqrt(128)

    // ldmatrix per-lane source row/col within V tile
    uint32_t vbase = (uint32_t)__cvta_generic_to_shared(Vs);
    int vrow = lane & 15;
    int vcol4 = (lane >> 4) * 4;             // uint offset (8 halves)

    // Stage Q (scaled + fp16)
    const float* qb = q + ((size_t)(b*S + qt*128))*C + head*HD;
    #pragma unroll
    for (int i = 0; i < 16; i++) {
        int idx = tid + i*256;
        int row = idx >> 5, c4 = idx & 31;
        float4 t = *(const float4*)(qb + (size_t)row*C + c4*4);
        *(uint2*)&Qs[row*QK_ST + c4*2] =
            make_uint2(packh2(t.x*SC, t.y*SC), packh2(t.z*SC, t.w*SC));
    }

    float oacc[16][4];
    #pragma unroll
    for (int nt = 0; nt < 16; nt++)
        #pragma unroll
        for (int j = 0; j < 4; j++) oacc[nt][j] = 0.f;
    float m0 = -1e30f, m1 = -1e30f, l0 = 0.f, l1 = 0.f;

    int ntiles = (seqlen + 63) >> 6;
    const float* kb = k + ((size_t)(b*S))*C + head*HD;
    const float* vb = v + ((size_t)(b*S))*C + head*HD;

    for (int kt = 0; kt < ntiles; kt++) {
        __syncthreads();
        #pragma unroll
        for (int i = 0; i < 8; i++) {
            int idx = tid + i*256;
            int row = idx >> 5, c4 = idx & 31;
            size_t goff = (size_t)(kt*64 + row)*C + c4*4;
            float4 t = *(const float4*)(kb + goff);
            *(uint2*)&Ks[row*QK_ST + c4*2] =
                make_uint2(packh2(t.x, t.y), packh2(t.z, t.w));
            float4 u = *(const float4*)(vb + goff);
            *(uint2*)&Vs[row*QK_ST + c4*2] =
                make_uint2(packh2(u.x, u.y), packh2(u.z, u.w));
        }
        __syncthreads();

        // S = Q K^T   (8 k-steps of k16 over d=128)
        float sacc[8][4];
        #pragma unroll
        for (int nt = 0; nt < 8; nt++)
            #pragma unroll
            for (int j = 0; j < 4; j++) sacc[nt][j] = 0.f;

        #pragma unroll
        for (int ks = 0; ks < 8; ks++) {
            unsigned a0 = Qs[(qrow+gr  )*QK_ST + ks*8 + gc    ];
            unsigned a1 = Qs[(qrow+gr+8)*QK_ST + ks*8 + gc    ];
            unsigned a2 = Qs[(qrow+gr  )*QK_ST + ks*8 + gc + 4];
            unsigned a3 = Qs[(qrow+gr+8)*QK_ST + ks*8 + gc + 4];
            #pragma unroll
            for (int nt = 0; nt < 8; nt++) {
                unsigned b0 = Ks[(nt*8+gr)*QK_ST + ks*8 + gc    ];
                unsigned b1 = Ks[(nt*8+gr)*QK_ST + ks*8 + gc + 4];
                mma_f16(sacc[nt], a0, a1, a2, a3, b0, b1);
            }
        }

        // mask (last partial tile only)
        if (kt*64 + 64 > seqlen) {
            #pragma unroll
            for (int nt = 0; nt < 8; nt++) {
                int c0 = kt*64 + nt*8 + 2*gc;
                if (c0     >= seqlen) { sacc[nt][0] = -1e30f; sacc[nt][2] = -1e30f; }
                if (c0 + 1 >= seqlen) { sacc[nt][1] = -1e30f; sacc[nt][3] = -1e30f; }
            }
        }

        // online softmax (fp32); rows gr (regs 0,1) and gr+8 (regs 2,3)
        float rm0 = -1e30f, rm1 = -1e30f;
        #pragma unroll
        for (int nt = 0; nt < 8; nt++) {
            rm0 = fmaxf(rm0, fmaxf(sacc[nt][0], sacc[nt][1]));
            rm1 = fmaxf(rm1, fmaxf(sacc[nt][2], sacc[nt][3]));
        }
        rm0 = fmaxf(rm0, __shfl_xor_sync(0xffffffffu, rm0, 1));
        rm0 = fmaxf(rm0, __shfl_xor_sync(0xffffffffu, rm0, 2));
        rm1 = fmaxf(rm1, __shfl_xor_sync(0xffffffffu, rm1, 1));
        rm1 = fmaxf(rm1, __shfl_xor_sync(0xffffffffu, rm1, 2));
        float mn0 = fmaxf(m0, rm0), mn1 = fmaxf(m1, rm1);
        float al0 = __expf(m0 - mn0), al1 = __expf(m1 - mn1);
        #pragma unroll
        for (int nt = 0; nt < 16; nt++) {
            oacc[nt][0] *= al0; oacc[nt][1] *= al0;
            oacc[nt][2] *= al1; oacc[nt][3] *= al1;
        }
        float ps0 = 0.f, ps1 = 0.f;
        #pragma unroll
        for (int nt = 0; nt < 8; nt++) {
            float p0 = __expf(sacc[nt][0] - mn0);
            float p1 = __expf(sacc[nt][1] - mn0);
            float p2 = __expf(sacc[nt][2] - mn1);
            float p3 = __expf(sacc[nt][3] - mn1);
            ps0 += p0 + p1;
            ps1 += p2 + p3;
            Ps[(qrow+gr  )*PS_ST + nt*4 + gc] = packh2(p0, p1);
            Ps[(qrow+gr+8)*PS_ST + nt*4 + gc] = packh2(p2, p3);
        }
        ps0 += __shfl_xor_sync(0xffffffffu, ps0, 1);
        ps0 += __shfl_xor_sync(0xffffffffu, ps0, 2);
        ps1 += __shfl_xor_sync(0xffffffffu, ps1, 1);
        ps1 += __shfl_xor_sync(0xffffffffu, ps1, 2);
        l0 = l0*al0 + ps0; m0 = mn0;
        l1 = l1*al1 + ps1; m1 = mn1;
        __syncwarp();

        // O += P V   (4 k-steps of k16 over 64 keys; V frags via ldmatrix.trans)
        #pragma unroll
        for (int ks2 = 0; ks2 < 4; ks2++) {
            unsigned a0 = Ps[(qrow+gr  )*PS_ST + ks2*8 + gc    ];
            unsigned a1 = Ps[(qrow+gr+8)*PS_ST + ks2*8 + gc    ];
            unsigned a2 = Ps[(qrow+gr  )*PS_ST + ks2*8 + gc + 4];
            unsigned a3 = Ps[(qrow+gr+8)*PS_ST + ks2*8 + gc + 4];
            uint32_t va = vbase + (uint32_t)(((ks2*16 + vrow)*QK_ST + vcol4) * 4);
            #pragma unroll
            for (int ntp = 0; ntp < 8; ntp++) {
                unsigned m0r, m1r, m2r, m3r;
                ldmx4t(m0r, m1r, m2r, m3r, va + ntp*32);
                mma_f16(oacc[2*ntp  ], a0, a1, a2, a3, m0r, m1r);
                mma_f16(oacc[2*ntp+1], a0, a1, a2, a3, m2r, m3r);
            }
        }
        __syncwarp();
    }

    float inv0 = 1.0f / l0, inv1 = 1.0f / l1;
    float* ob = out + ((size_t)(b*S + qt*128 + qrow + gr))*C + head*HD;
    #pragma unroll
    for (int nt2 = 0; nt2 < 16; nt2++) {
        int col = nt2*8 + 2*gc;
        *(float2*)(ob + col) =
            make_float2(oacc[nt2][0]*inv0, oacc[nt2][1]*inv0);
        *(float2*)(ob + (size_t)8*C + col) =
            make_float2(oacc[nt2][2]*inv1, oacc[nt2][3]*inv1);
    }
}

// ---------------------------------------------------------------------------
extern "C" void kernel_launch(void* const* d_in, const int* in_sizes, int n_in,
                              void* d_out, int out_size)
{
    const float* x     = (const float*)d_in[0];
    const int*   seq   = (const int*)  d_in[1];
    const float* freqs = (const float*)d_in[3];
    const float* Wq    = (const float*)d_in[4];
    const float* bq    = (const float*)d_in[5];
    const float* Wk    = (const float*)d_in[6];
    const float* bk    = (const float*)d_in[7];
    const float* Wv    = (const float*)d_in[8];
    const float* bv    = (const float*)d_in[9];
    const float* Wo    = (const float*)d_in[10];
    const float* bo    = (const float*)d_in[11];
    const float* nqw   = (const float*)d_in[12];
    const float* nkw   = (const float*)d_in[13];
    float* out = (float*)d_out;

    float *pq, *pk, *pv, *po;
    cudaGetSymbolAddress((void**)&pq, g_q);
    cudaGetSymbolAddress((void**)&pk, g_k);
    cudaGetSymbolAddress((void**)&pv, g_v);
    cudaGetSymbolAddress((void**)&po, g_o);

    cudaFuncSetAttribute(flash_f16,
                         cudaFuncAttributeMaxDynamicSharedMemorySize, FA_SMEM);

    dim3 gg(C/128, BS/128);
    sgemm_f16<<<gg, 256>>>(x, Wq, bq, pq, BS, C, C);
    sgemm_f16<<<gg, 256>>>(x, Wk, bk, pk, BS, C, C);
    sgemm_f16<<<gg, 256>>>(x, Wv, bv, pv, BS, C, C);
    rmsnorm_rope<<<BS, 256>>>(pq, nqw, freqs);
    rmsnorm_rope<<<BS, 256>>>(pk, nkw, freqs);

    flash_f16<<<dim3(S/128, NH, B), 256, FA_SMEM>>>(pq, pk, pv, seq, po);

    sgemm_f16<<<gg, 256>>>(po, Wo, bo, out, BS, C, C);
}

// round 12
// speedup vs baseline: 5.1304x; 1.0000x over previous
#include <cuda_runtime.h>
#include <cuda_fp16.h>
#include <math.h>
#include <stdint.h>

#define B 2
#define S 3072
#define C 1536
#define NH 12
#define HD 128
#define BS (B*S)

// Scratch (allocation-free rule: device globals)
__device__ float g_q[BS*C];
__device__ float g_k[BS*C];
__device__ float g_v[BS*C];
__device__ float g_o[BS*C];

// ---------------------------------------------------------------------------
// helpers
// ---------------------------------------------------------------------------
__device__ __forceinline__ unsigned packh2(float x, float y) {
    __half2 h = __floats2half2_rn(x, y);
    return *reinterpret_cast<unsigned*>(&h);
}

// fp16 mma, fp32 accumulate: D(16x8) += A(16x16) * B(16x8)
__device__ __forceinline__ void mma_f16(float* d,
    unsigned a0, unsigned a1, unsigned a2, unsigned a3,
    unsigned b0, unsigned b1)
{
    asm volatile(
        "mma.sync.aligned.m16n8k16.row.col.f32.f16.f16.f32 "
        "{%0,%1,%2,%3}, {%4,%5,%6,%7}, {%8,%9}, {%0,%1,%2,%3};\n"
        : "+f"(d[0]), "+f"(d[1]), "+f"(d[2]), "+f"(d[3])
        : "r"(a0), "r"(a1), "r"(a2), "r"(a3), "r"(b0), "r"(b1));
}

__device__ __forceinline__ void ldmx4(unsigned& r0, unsigned& r1,
                                      unsigned& r2, unsigned& r3, uint32_t a)
{
    asm volatile(
        "ldmatrix.sync.aligned.m8n8.x4.shared.b16 {%0,%1,%2,%3}, [%4];"
        : "=r"(r0), "=r"(r1), "=r"(r2), "=r"(r3) : "r"(a));
}

__device__ __forceinline__ void ldmx4t(unsigned& r0, unsigned& r1,
                                       unsigned& r2, unsigned& r3, uint32_t a)
{
    asm volatile(
        "ldmatrix.sync.aligned.m8n8.x4.trans.shared.b16 {%0,%1,%2,%3}, [%4];"
        : "=r"(r0), "=r"(r1), "=r"(r2), "=r"(r3) : "r"(a));
}

// ---------------------------------------------------------------------------
// fp16 GEMM: Cout[m][n] = sum_k A[m][k]*W[n][k] + bias[n]
// 128x128 tile, BK=32 halves, 8 warps, warp tile 32x64.
// Double-buffered smem (one __syncthreads per chunk, LDG ahead of compute).
// Fragments via ldmatrix.x4: row stride 20 uints (80B) -> conflict-free phases.
// ---------------------------------------------------------------------------
#define GST 20
#define GBUF (128*GST)

__global__ __launch_bounds__(256) void sgemm_f16(
    const float* __restrict__ A, const float* __restrict__ W,
    const float* __restrict__ bias, float* __restrict__ Cout,
    int M, int N, int K)
{
    __shared__ unsigned As[2*GBUF];
    __shared__ unsigned Bs[2*GBUF];
    int tid  = threadIdx.x;
    int bm   = blockIdx.y*128, bn = blockIdx.x*128;
    int lr   = tid >> 3, lc = tid & 7;     // staging: base row, float4 group
    int wid  = tid >> 5, lane = tid & 31;
    int wm   = wid & 3, wn = wid >> 2;
    int gr   = lane >> 2, gc = lane & 3;
    int lmr  = lane & 15, lmc = (lane >> 4) * 4;

    uint32_t asb = (uint32_t)__cvta_generic_to_shared(As);
    uint32_t bsb = (uint32_t)__cvta_generic_to_shared(Bs);

    const float* Ap = A + (size_t)(bm + lr) * K;
    const float* Wp = W + (size_t)(bn + lr) * K;

    float acc[2][8][4];
    #pragma unroll
    for (int mt = 0; mt < 2; mt++)
        #pragma unroll
        for (int nt = 0; nt < 8; nt++)
            #pragma unroll
            for (int j = 0; j < 4; j++) acc[mt][nt][j] = 0.f;

    const int nch = K / 32;   // 48
    float4 av[4], wv[4];

    // prologue: chunk 0
    #pragma unroll
    for (int i = 0; i < 4; i++) {
        av[i] = *(const float4*)(Ap + (size_t)(i*32)*K + lc*4);
        wv[i] = *(const float4*)(Wp + (size_t)(i*32)*K + lc*4);
    }
    #pragma unroll
    for (int i = 0; i < 4; i++) {
        int row = lr + i*32;
        *(uint2*)&As[row*GST + lc*2] =
            make_uint2(packh2(av[i].x, av[i].y), packh2(av[i].z, av[i].w));
        *(uint2*)&Bs[row*GST + lc*2] =
            make_uint2(packh2(wv[i].x, wv[i].y), packh2(wv[i].z, wv[i].w));
    }
    __syncthreads();

    for (int ch = 0; ch < nch; ch++) {
        int buf = ch & 1;
        bool more = (ch + 1 < nch);
        if (more) {
            int k0 = (ch + 1) * 32;
            #pragma unroll
            for (int i = 0; i < 4; i++) {
                av[i] = *(const float4*)(Ap + (size_t)(i*32)*K + k0 + lc*4);
                wv[i] = *(const float4*)(Wp + (size_t)(i*32)*K + k0 + lc*4);
            }
        }

        uint32_t ab = asb + buf * (GBUF*4);
        uint32_t bb = bsb + buf * (GBUF*4);
        #pragma unroll
        for (int ks = 0; ks < 2; ks++) {
            unsigned af[2][4];
            #pragma unroll
            for (int mt = 0; mt < 2; mt++)
                ldmx4(af[mt][0], af[mt][1], af[mt][2], af[mt][3],
                      ab + (uint32_t)(((wm*32 + mt*16 + lmr)*GST + ks*8 + lmc)*4));
            #pragma unroll
            for (int ntp = 0; ntp < 4; ntp++) {
                unsigned b0, b1, b2, b3;
                ldmx4(b0, b1, b2, b3,
                      bb + (uint32_t)(((wn*64 + ntp*16 + lmr)*GST + ks*8 + lmc)*4));
                mma_f16(acc[0][2*ntp  ], af[0][0],af[0][1],af[0][2],af[0][3], b0, b2);
                mma_f16(acc[0][2*ntp+1], af[0][0],af[0][1],af[0][2],af[0][3], b1, b3);
                mma_f16(acc[1][2*ntp  ], af[1][0],af[1][1],af[1][2],af[1][3], b0, b2);
                mma_f16(acc[1][2*ntp+1], af[1][0],af[1][1],af[1][2],af[1][3], b1, b3);
            }
        }

        if (more) {
            unsigned* Ad = As + (buf ^ 1) * GBUF;
            unsigned* Bd = Bs + (buf ^ 1) * GBUF;
            #pragma unroll
            for (int i = 0; i < 4; i++) {
                int row = lr + i*32;
                *(uint2*)&Ad[row*GST + lc*2] =
                    make_uint2(packh2(av[i].x, av[i].y), packh2(av[i].z, av[i].w));
                *(uint2*)&Bd[row*GST + lc*2] =
                    make_uint2(packh2(wv[i].x, wv[i].y), packh2(wv[i].z, wv[i].w));
            }
        }
        __syncthreads();
    }

    #pragma unroll
    for (int mt = 0; mt < 2; mt++) {
        int r0 = bm + wm*32 + mt*16 + gr;
        #pragma unroll
        for (int nt = 0; nt < 8; nt++) {
            int col = bn + wn*64 + nt*8 + 2*gc;
            float2 bb = *(const float2*)(bias + col);
            float2 o0 = make_float2(acc[mt][nt][0] + bb.x, acc[mt][nt][1] + bb.y);
            float2 o1 = make_float2(acc[mt][nt][2] + bb.x, acc[mt][nt][3] + bb.y);
            *(float2*)&Cout[(size_t)r0*N + col]     = o0;
            *(float2*)&Cout[(size_t)(r0+8)*N + col] = o1;
        }
    }
}

// ---------------------------------------------------------------------------
// Fused RMSNorm + RoPE (unchanged, proven)
// ---------------------------------------------------------------------------
__global__ __launch_bounds__(256) void rmsnorm_rope(
    float* __restrict__ t, const float* __restrict__ nw,
    const float* __restrict__ freqs)
{
    int bs = blockIdx.x;
    int s = bs % S;
    int tid = threadIdx.x;
    float2* row = (float2*)(t + (size_t)bs * C);
    const float2* wr = (const float2*)nw;

    float2 pv[3], pw[3];
    float ss = 0.f;
    #pragma unroll
    for (int i = 0; i < 3; i++) {
        pv[i] = row[tid + i*256];
        pw[i] = wr[tid + i*256];
        ss += pv[i].x*pv[i].x + pv[i].y*pv[i].y;
    }
    #pragma unroll
    for (int off = 16; off; off >>= 1)
        ss += __shfl_xor_sync(0xffffffffu, ss, off);

    __shared__ float red[8];
    __shared__ float cs[64], sn[64];
    if ((tid & 31) == 0) red[tid >> 5] = ss;
    __syncthreads();
    if (tid < 32) {
        float tsum = (tid < 8) ? red[tid] : 0.f;
        #pragma unroll
        for (int off = 4; off; off >>= 1)
            tsum += __shfl_xor_sync(0xffffffffu, tsum, off);
        if (tid == 0) red[0] = tsum;
    }
    if (tid >= 64 && tid < 128) {
        int j = tid - 64;
        int f = s / 768, r = s % 768, h = r / 32, w = r % 32;
        int sel = (j < 22) ? f : ((j < 43) ? h : w);
        float ang = freqs[sel*64 + j];
        cs[j] = cosf(ang);
        sn[j] = sinf(ang);
    }
    __syncthreads();

    float scale = rsqrtf(red[0] * (1.0f / C) + 1e-6f);
    #pragma unroll
    for (int i = 0; i < 3; i++) {
        int p = tid + i*256;
        int ci = p & 63;
        float e = pv[i].x * scale * pw[i].x;
        float o = pv[i].y * scale * pw[i].y;
        float2 ro;
        ro.x = e*cs[ci] - o*sn[ci];
        ro.y = e*sn[ci] + o*cs[ci];
        row[tid + i*256] = ro;
    }
}

// ---------------------------------------------------------------------------
// fp16 flash attention: BM=128 queries, BN=64 keys, d=128.
// 8 warps, one 16-row stripe each. All mma fragments via ldmatrix.x4
// (Q/K/P non-trans, V trans). Softmax fp32, P staged fp16 in smem.
// ---------------------------------------------------------------------------
#define QK_ST 68
#define PS_ST 36
#define OFF_K (128*QK_ST)
#define OFF_V (OFF_K + 64*QK_ST)
#define OFF_P (OFF_V + 64*QK_ST)
#define FA_SMEM ((OFF_P + 128*PS_ST) * 4)

__global__ __launch_bounds__(256) void flash_f16(
    const float* __restrict__ q, const float* __restrict__ k,
    const float* __restrict__ v, const int* __restrict__ seq_lens,
    float* __restrict__ out)
{
    extern __shared__ unsigned sm[];
    unsigned* Qs = sm;
    unsigned* Ks = sm + OFF_K;
    unsigned* Vs = sm + OFF_V;
    unsigned* Ps = sm + OFF_P;

    int qt = blockIdx.x, head = blockIdx.y, b = blockIdx.z;
    int tid = threadIdx.x;
    int wid = tid >> 5, lane = tid & 31;
    int gr = lane >> 2, gc = lane & 3;
    int qrow = wid * 16;
    int seqlen = seq_lens[b];
    const float SC = 0.08838834764831845f;   // 1/sqrt(128)

    uint32_t qsb = (uint32_t)__cvta_generic_to_shared(Qs);
    uint32_t ksb = (uint32_t)__cvta_generic_to_shared(Ks);
    uint32_t vsb = (uint32_t)__cvta_generic_to_shared(Vs);
    uint32_t psb = (uint32_t)__cvta_generic_to_shared(Ps);
    int lmr = lane & 15, lmc = (lane >> 4) * 4;
    int vrow = lane & 15, vcol4 = (lane >> 4) * 4;

    // Stage Q (scaled + fp16)
    const float* qb = q + ((size_t)(b*S + qt*128))*C + head*HD;
    #pragma unroll
    for (int i = 0; i < 16; i++) {
        int idx = tid + i*256;
        int row = idx >> 5, c4 = idx & 31;
        float4 t = *(const float4*)(qb + (size_t)row*C + c4*4);
        *(uint2*)&Qs[row*QK_ST + c4*2] =
            make_uint2(packh2(t.x*SC, t.y*SC), packh2(t.z*SC, t.w*SC));
    }

    float oacc[16][4];
    #pragma unroll
    for (int nt = 0; nt < 16; nt++)
        #pragma unroll
        for (int j = 0; j < 4; j++) oacc[nt][j] = 0.f;
    float m0 = -1e30f, m1 = -1e30f, l0 = 0.f, l1 = 0.f;

    int ntiles = (seqlen + 63) >> 6;
    const float* kb = k + ((size_t)(b*S))*C + head*HD;
    const float* vb = v + ((size_t)(b*S))*C + head*HD;

    for (int kt = 0; kt < ntiles; kt++) {
        __syncthreads();
        #pragma unroll
        for (int i = 0; i < 8; i++) {
            int idx = tid + i*256;
            int row = idx >> 5, c4 = idx & 31;
            size_t goff = (size_t)(kt*64 + row)*C + c4*4;
            float4 t = *(const float4*)(kb + goff);
            *(uint2*)&Ks[row*QK_ST + c4*2] =
                make_uint2(packh2(t.x, t.y), packh2(t.z, t.w));
            float4 u = *(const float4*)(vb + goff);
            *(uint2*)&Vs[row*QK_ST + c4*2] =
                make_uint2(packh2(u.x, u.y), packh2(u.z, u.w));
        }
        __syncthreads();

        // S = Q K^T   (8 k-steps of k16 over d=128), all ldmatrix
        float sacc[8][4];
        #pragma unroll
        for (int nt = 0; nt < 8; nt++)
            #pragma unroll
            for (int j = 0; j < 4; j++) sacc[nt][j] = 0.f;

        #pragma unroll
        for (int ks = 0; ks < 8; ks++) {
            unsigned a0, a1, a2, a3;
            ldmx4(a0, a1, a2, a3,
                  qsb + (uint32_t)(((qrow + lmr)*QK_ST + ks*8 + lmc)*4));
            #pragma unroll
            for (int ntp = 0; ntp < 4; ntp++) {
                unsigned b0, b1, b2, b3;
                ldmx4(b0, b1, b2, b3,
                      ksb + (uint32_t)(((ntp*16 + lmr)*QK_ST + ks*8 + lmc)*4));
                mma_f16(sacc[2*ntp  ], a0, a1, a2, a3, b0, b2);
                mma_f16(sacc[2*ntp+1], a0, a1, a2, a3, b1, b3);
            }
        }

        // mask (last partial tile only)
        if (kt*64 + 64 > seqlen) {
            #pragma unroll
            for (int nt = 0; nt < 8; nt++) {
                int c0 = kt*64 + nt*8 + 2*gc;
                if (c0     >= seqlen) { sacc[nt][0] = -1e30f; sacc[nt][2] = -1e30f; }
                if (c0 + 1 >= seqlen) { sacc[nt][1] = -1e30f; sacc[nt][3] = -1e30f; }
            }
        }

        // online softmax (fp32); rows gr (regs 0,1) and gr+8 (regs 2,3)
        float rm0 = -1e30f, rm1 = -1e30f;
        #pragma unroll
        for (int nt = 0; nt < 8; nt++) {
            rm0 = fmaxf(rm0, fmaxf(sacc[nt][0], sacc[nt][1]));
            rm1 = fmaxf(rm1, fmaxf(sacc[nt][2], sacc[nt][3]));
        }
        rm0 = fmaxf(rm0, __shfl_xor_sync(0xffffffffu, rm0, 1));
        rm0 = fmaxf(rm0, __shfl_xor_sync(0xffffffffu, rm0, 2));
        rm1 = fmaxf(rm1, __shfl_xor_sync(0xffffffffu, rm1, 1));
        rm1 = fmaxf(rm1, __shfl_xor_sync(0xffffffffu, rm1, 2));
        float mn0 = fmaxf(m0, rm0), mn1 = fmaxf(m1, rm1);
        float al0 = __expf(m0 - mn0), al1 = __expf(m1 - mn1);
        #pragma unroll
        for (int nt = 0; nt < 16; nt++) {
            oacc[nt][0] *= al0; oacc[nt][1] *= al0;
            oacc[nt][2] *= al1; oacc[nt][3] *= al1;
        }
        float ps0 = 0.f, ps1 = 0.f;
        #pragma unroll
        for (int nt = 0; nt < 8; nt++) {
            float p0 = __expf(sacc[nt][0] - mn0);
            float p1 = __expf(sacc[nt][1] - mn0);
            float p2 = __expf(sacc[nt][2] - mn1);
            float p3 = __expf(sacc[nt][3] - mn1);
            ps0 += p0 + p1;
            ps1 += p2 + p3;
            Ps[(qrow+gr  )*PS_ST + nt*4 + gc] = packh2(p0, p1);
            Ps[(qrow+gr+8)*PS_ST + nt*4 + gc] = packh2(p2, p3);
        }
        ps0 += __shfl_xor_sync(0xffffffffu, ps0, 1);
        ps0 += __shfl_xor_sync(0xffffffffu, ps0, 2);
        ps1 += __shfl_xor_sync(0xffffffffu, ps1, 1);
        ps1 += __shfl_xor_sync(0xffffffffu, ps1, 2);
        l0 = l0*al0 + ps0; m0 = mn0;
        l1 = l1*al1 + ps1; m1 = mn1;
        __syncwarp();

        // O += P V   (4 k-steps of k16 over 64 keys)
        #pragma unroll
        for (int ks2 = 0; ks2 < 4; ks2++) {
            unsigned a0, a1, a2, a3;
            ldmx4(a0, a1, a2, a3,
                  psb + (uint32_t)(((qrow + lmr)*PS_ST + ks2*8 + lmc)*4));
            uint32_t va = vsb + (uint32_t)(((ks2*16 + vrow)*QK_ST + vcol4) * 4);
            #pragma unroll
            for (int ntp = 0; ntp < 8; ntp++) {
                unsigned m0r, m1r, m2r, m3r;
                ldmx4t(m0r, m1r, m2r, m3r, va + ntp*32);
                mma_f16(oacc[2*ntp  ], a0, a1, a2, a3, m0r, m1r);
                mma_f16(oacc[2*ntp+1], a0, a1, a2, a3, m2r, m3r);
            }
        }
        __syncwarp();
    }

    float inv0 = 1.0f / l0, inv1 = 1.0f / l1;
    float* ob = out + ((size_t)(b*S + qt*128 + qrow + gr))*C + head*HD;
    #pragma unroll
    for (int nt2 = 0; nt2 < 16; nt2++) {
        int col = nt2*8 + 2*gc;
        *(float2*)(ob + col) =
            make_float2(oacc[nt2][0]*inv0, oacc[nt2][1]*inv0);
        *(float2*)(ob + (size_t)8*C + col) =
            make_float2(oacc[nt2][2]*inv1, oacc[nt2][3]*inv1);
    }
}

// ---------------------------------------------------------------------------
extern "C" void kernel_launch(void* const* d_in, const int* in_sizes, int n_in,
                              void* d_out, int out_size)
{
    const float* x     = (const float*)d_in[0];
    const int*   seq   = (const int*)  d_in[1];
    const float* freqs = (const float*)d_in[3];
    const float* Wq    = (const float*)d_in[4];
    const float* bq    = (const float*)d_in[5];
    const float* Wk    = (const float*)d_in[6];
    const float* bk    = (const float*)d_in[7];
    const float* Wv    = (const float*)d_in[8];
    const float* bv    = (const float*)d_in[9];
    const float* Wo    = (const float*)d_in[10];
    const float* bo    = (const float*)d_in[11];
    const float* nqw   = (const float*)d_in[12];
    const float* nkw   = (const float*)d_in[13];
    float* out = (float*)d_out;

    float *pq, *pk, *pv, *po;
    cudaGetSymbolAddress((void**)&pq, g_q);
    cudaGetSymbolAddress((void**)&pk, g_k);
    cudaGetSymbolAddress((void**)&pv, g_v);
    cudaGetSymbolAddress((void**)&po, g_o);

    cudaFuncSetAttribute(flash_f16,
                         cudaFuncAttributeMaxDynamicSharedMemorySize, FA_SMEM);

    dim3 gg(C/128, BS/128);
    sgemm_f16<<<gg, 256>>>(x, Wq, bq, pq, BS, C, C);
    sgemm_f16<<<gg, 256>>>(x, Wk, bk, pk, BS, C, C);
    sgemm_f16<<<gg, 256>>>(x, Wv, bv, pv, BS, C, C);
    rmsnorm_rope<<<BS, 256>>>(pq, nqw, freqs);
    rmsnorm_rope<<<BS, 256>>>(pk, nkw, freqs);

    flash_f16<<<dim3(S/128, NH, B), 256, FA_SMEM>>>(pq, pk, pv, seq, po);

    sgemm_f16<<<gg, 256>>>(po, Wo, bo, out, BS, C, C);
}

// round 13
// speedup vs baseline: 6.5590x; 1.2785x over previous
#include <cuda_runtime.h>
#include <cuda_fp16.h>
#include <math.h>
#include <stdint.h>

#define B 2
#define S 3072
#define C 1536
#define NH 12
#define HD 128
#define BS (B*S)
#define CC (C*C)

// Scratch (allocation-free rule: device globals)
__device__ float  g_q [BS*C];          // Q projection, fp32 (pre-norm)
__device__ float  g_k [BS*C];          // K projection, fp32 (pre-norm)
__device__ __half g_xh[BS*C];          // x in fp16
__device__ __half g_wh[4*CC];          // Wq|Wk|Wv|Wo in fp16
__device__ __half g_qh[BS*C];          // Q normed+roped, fp16
__device__ __half g_kh[BS*C];          // K normed+roped, fp16
__device__ __half g_vh[BS*C];          // V, fp16
__device__ __half g_oh[BS*C];          // attention out, fp16

// ---------------------------------------------------------------------------
// helpers
// ---------------------------------------------------------------------------
__device__ __forceinline__ unsigned packh2(float x, float y) {
    __half2 h = __floats2half2_rn(x, y);
    return *reinterpret_cast<unsigned*>(&h);
}

__device__ __forceinline__ void mma_f16(float* d,
    unsigned a0, unsigned a1, unsigned a2, unsigned a3,
    unsigned b0, unsigned b1)
{
    asm volatile(
        "mma.sync.aligned.m16n8k16.row.col.f32.f16.f16.f32 "
        "{%0,%1,%2,%3}, {%4,%5,%6,%7}, {%8,%9}, {%0,%1,%2,%3};\n"
        : "+f"(d[0]), "+f"(d[1]), "+f"(d[2]), "+f"(d[3])
        : "r"(a0), "r"(a1), "r"(a2), "r"(a3), "r"(b0), "r"(b1));
}

__device__ __forceinline__ void ldmx4(unsigned& r0, unsigned& r1,
                                      unsigned& r2, unsigned& r3, uint32_t a)
{
    asm volatile(
        "ldmatrix.sync.aligned.m8n8.x4.shared.b16 {%0,%1,%2,%3}, [%4];"
        : "=r"(r0), "=r"(r1), "=r"(r2), "=r"(r3) : "r"(a));
}

__device__ __forceinline__ void ldmx4t(unsigned& r0, unsigned& r1,
                                       unsigned& r2, unsigned& r3, uint32_t a)
{
    asm volatile(
        "ldmatrix.sync.aligned.m8n8.x4.trans.shared.b16 {%0,%1,%2,%3}, [%4];"
        : "=r"(r0), "=r"(r1), "=r"(r2), "=r"(r3) : "r"(a));
}

// ---------------------------------------------------------------------------
// one-shot fp32 -> fp16 conversion (n multiple of 4)
// ---------------------------------------------------------------------------
__global__ __launch_bounds__(256) void f2h(
    const float* __restrict__ s, __half* __restrict__ d)
{
    int i = blockIdx.x * 256 + threadIdx.x;
    float4 v = ((const float4*)s)[i];
    ((uint2*)d)[i] = make_uint2(packh2(v.x, v.y), packh2(v.z, v.w));
}

// ---------------------------------------------------------------------------
// fp16 GEMM (fp16 inputs): Cout[m][n] = sum_k A[m][k]*W[n][k] + bias[n]
// 128x128 tile, BK=32, 8 warps, warp tile 32x64, double-buffered.
// Staging is a pure fp16 copy: 2x LDG.128 + 2x STS.128 per matrix per thread.
// HOUT: write fp16 (for V), else fp32.
// ---------------------------------------------------------------------------
#define GST 20
#define GBUF (128*GST)

template<bool HOUT>
__global__ __launch_bounds__(256) void hgemm(
    const __half* __restrict__ Ah, const __half* __restrict__ Wh,
    const float* __restrict__ bias, void* __restrict__ CoutV,
    int M, int N, int K)
{
    __shared__ unsigned As[2*GBUF];
    __shared__ unsigned Bs[2*GBUF];
    int tid  = threadIdx.x;
    int bm   = blockIdx.y*128, bn = blockIdx.x*128;
    int lr2  = tid >> 2, lc2 = tid & 3;    // staging: base row, 16B group
    int wid  = tid >> 5, lane = tid & 31;
    int wm   = wid & 3, wn = wid >> 2;
    int gr   = lane >> 2, gc = lane & 3;
    int lmr  = lane & 15, lmc = (lane >> 4) * 4;

    uint32_t asb = (uint32_t)__cvta_generic_to_shared(As);
    uint32_t bsb = (uint32_t)__cvta_generic_to_shared(Bs);

    const __half* Ap = Ah + (size_t)(bm + lr2) * K;
    const __half* Wp = Wh + (size_t)(bn + lr2) * K;

    float acc[2][8][4];
    #pragma unroll
    for (int mt = 0; mt < 2; mt++)
        #pragma unroll
        for (int nt = 0; nt < 8; nt++)
            #pragma unroll
            for (int j = 0; j < 4; j++) acc[mt][nt][j] = 0.f;

    const int nch = K / 32;   // 48
    uint4 a0, a1, w0, w1;

    // prologue: chunk 0 -> buf 0
    a0 = *(const uint4*)(Ap + lc2*8);
    a1 = *(const uint4*)(Ap + (size_t)64*K + lc2*8);
    w0 = *(const uint4*)(Wp + lc2*8);
    w1 = *(const uint4*)(Wp + (size_t)64*K + lc2*8);
    *(uint4*)&As[lr2*GST + lc2*4]      = a0;
    *(uint4*)&As[(lr2+64)*GST + lc2*4] = a1;
    *(uint4*)&Bs[lr2*GST + lc2*4]      = w0;
    *(uint4*)&Bs[(lr2+64)*GST + lc2*4] = w1;
    __syncthreads();

    for (int ch = 0; ch < nch; ch++) {
        int buf = ch & 1;
        bool more = (ch + 1 < nch);
        if (more) {
            int k0 = (ch + 1) * 32;
            a0 = *(const uint4*)(Ap + k0 + lc2*8);
            a1 = *(const uint4*)(Ap + (size_t)64*K + k0 + lc2*8);
            w0 = *(const uint4*)(Wp + k0 + lc2*8);
            w1 = *(const uint4*)(Wp + (size_t)64*K + k0 + lc2*8);
        }

        uint32_t ab = asb + buf * (GBUF*4);
        uint32_t bb = bsb + buf * (GBUF*4);
        #pragma unroll
        for (int ks = 0; ks < 2; ks++) {
            unsigned af[2][4];
            #pragma unroll
            for (int mt = 0; mt < 2; mt++)
                ldmx4(af[mt][0], af[mt][1], af[mt][2], af[mt][3],
                      ab + (uint32_t)(((wm*32 + mt*16 + lmr)*GST + ks*8 + lmc)*4));
            #pragma unroll
            for (int ntp = 0; ntp < 4; ntp++) {
                unsigned b0, b1, b2, b3;
                ldmx4(b0, b1, b2, b3,
                      bb + (uint32_t)(((wn*64 + ntp*16 + lmr)*GST + ks*8 + lmc)*4));
                mma_f16(acc[0][2*ntp  ], af[0][0],af[0][1],af[0][2],af[0][3], b0, b2);
                mma_f16(acc[0][2*ntp+1], af[0][0],af[0][1],af[0][2],af[0][3], b1, b3);
                mma_f16(acc[1][2*ntp  ], af[1][0],af[1][1],af[1][2],af[1][3], b0, b2);
                mma_f16(acc[1][2*ntp+1], af[1][0],af[1][1],af[1][2],af[1][3], b1, b3);
            }
        }

        if (more) {
            unsigned* Ad = As + (buf ^ 1) * GBUF;
            unsigned* Bd = Bs + (buf ^ 1) * GBUF;
            *(uint4*)&Ad[lr2*GST + lc2*4]      = a0;
            *(uint4*)&Ad[(lr2+64)*GST + lc2*4] = a1;
            *(uint4*)&Bd[lr2*GST + lc2*4]      = w0;
            *(uint4*)&Bd[(lr2+64)*GST + lc2*4] = w1;
        }
        __syncthreads();
    }

    #pragma unroll
    for (int mt = 0; mt < 2; mt++) {
        int r0 = bm + wm*32 + mt*16 + gr;
        #pragma unroll
        for (int nt = 0; nt < 8; nt++) {
            int col = bn + wn*64 + nt*8 + 2*gc;
            float2 bb2 = *(const float2*)(bias + col);
            if (HOUT) {
                __half* Ch = (__half*)CoutV;
                *(unsigned*)&Ch[(size_t)r0*N + col] =
                    packh2(acc[mt][nt][0] + bb2.x, acc[mt][nt][1] + bb2.y);
                *(unsigned*)&Ch[(size_t)(r0+8)*N + col] =
                    packh2(acc[mt][nt][2] + bb2.x, acc[mt][nt][3] + bb2.y);
            } else {
                float* Cf = (float*)CoutV;
                *(float2*)&Cf[(size_t)r0*N + col] =
                    make_float2(acc[mt][nt][0] + bb2.x, acc[mt][nt][1] + bb2.y);
                *(float2*)&Cf[(size_t)(r0+8)*N + col] =
                    make_float2(acc[mt][nt][2] + bb2.x, acc[mt][nt][3] + bb2.y);
            }
        }
    }
}

// ---------------------------------------------------------------------------
// Fused RMSNorm + RoPE: fp32 in, fp16 out.
// ---------------------------------------------------------------------------
__global__ __launch_bounds__(256) void rmsnorm_rope(
    const float* __restrict__ t, __half* __restrict__ dsth,
    const float* __restrict__ nw, const float* __restrict__ freqs)
{
    int bs = blockIdx.x;
    int s = bs % S;
    int tid = threadIdx.x;
    const float2* row = (const float2*)(t + (size_t)bs * C);
    unsigned* drow = (unsigned*)(dsth + (size_t)bs * C);
    const float2* wr = (const float2*)nw;

    float2 pv[3], pw[3];
    float ss = 0.f;
    #pragma unroll
    for (int i = 0; i < 3; i++) {
        pv[i] = row[tid + i*256];
        pw[i] = wr[tid + i*256];
        ss += pv[i].x*pv[i].x + pv[i].y*pv[i].y;
    }
    #pragma unroll
    for (int off = 16; off; off >>= 1)
        ss += __shfl_xor_sync(0xffffffffu, ss, off);

    __shared__ float red[8];
    __shared__ float cs[64], sn[64];
    if ((tid & 31) == 0) red[tid >> 5] = ss;
    __syncthreads();
    if (tid < 32) {
        float tsum = (tid < 8) ? red[tid] : 0.f;
        #pragma unroll
        for (int off = 4; off; off >>= 1)
            tsum += __shfl_xor_sync(0xffffffffu, tsum, off);
        if (tid == 0) red[0] = tsum;
    }
    if (tid >= 64 && tid < 128) {
        int j = tid - 64;
        int f = s / 768, r = s % 768, h = r / 32, w = r % 32;
        int sel = (j < 22) ? f : ((j < 43) ? h : w);
        float ang = freqs[sel*64 + j];
        cs[j] = cosf(ang);
        sn[j] = sinf(ang);
    }
    __syncthreads();

    float scale = rsqrtf(red[0] * (1.0f / C) + 1e-6f);
    #pragma unroll
    for (int i = 0; i < 3; i++) {
        int p = tid + i*256;
        int ci = p & 63;
        float e = pv[i].x * scale * pw[i].x;
        float o = pv[i].y * scale * pw[i].y;
        drow[p] = packh2(e*cs[ci] - o*sn[ci], e*sn[ci] + o*cs[ci]);
    }
}

// ---------------------------------------------------------------------------
// fp16 flash attention: BM=128 queries, BN=64 keys, d=128. fp16 in/out.
// Staging is a pure fp16 copy. Softmax scale folded into exp2 argument.
// ---------------------------------------------------------------------------
#define QK_ST 68
#define PS_ST 36
#define OFF_K (128*QK_ST)
#define OFF_V (OFF_K + 64*QK_ST)
#define OFF_P (OFF_V + 64*QK_ST)
#define FA_SMEM ((OFF_P + 128*PS_ST) * 4)

__global__ __launch_bounds__(256) void flash_f16(
    const __half* __restrict__ q, const __half* __restrict__ k,
    const __half* __restrict__ v, const int* __restrict__ seq_lens,
    __half* __restrict__ out)
{
    extern __shared__ unsigned sm[];
    unsigned* Qs = sm;
    unsigned* Ks = sm + OFF_K;
    unsigned* Vs = sm + OFF_V;
    unsigned* Ps = sm + OFF_P;

    int qt = blockIdx.x, head = blockIdx.y, b = blockIdx.z;
    int tid = threadIdx.x;
    int wid = tid >> 5, lane = tid & 31;
    int gr = lane >> 2, gc = lane & 3;
    int qrow = wid * 16;
    int seqlen = seq_lens[b];
    // softmax scale * log2(e), applied inside exp2
    const float SCL2E = 0.08838834764831845f * 1.4426950408889634f;

    uint32_t qsb = (uint32_t)__cvta_generic_to_shared(Qs);
    uint32_t ksb = (uint32_t)__cvta_generic_to_shared(Ks);
    uint32_t vsb = (uint32_t)__cvta_generic_to_shared(Vs);
    uint32_t psb = (uint32_t)__cvta_generic_to_shared(Ps);
    int lmr = lane & 15, lmc = (lane >> 4) * 4;
    int vrow = lane & 15, vcol4 = (lane >> 4) * 4;

    // Stage Q: 128 rows x 16 16B-groups, pure copy
    const __half* qb = q + (size_t)(b*S + qt*128)*C + head*HD;
    #pragma unroll
    for (int i = 0; i < 8; i++) {
        int idx = tid + i*256;
        int row = idx >> 4, g = idx & 15;
        *(uint4*)&Qs[row*QK_ST + g*4] = *(const uint4*)(qb + (size_t)row*C + g*8);
    }

    float oacc[16][4];
    #pragma unroll
    for (int nt = 0; nt < 16; nt++)
        #pragma unroll
        for (int j = 0; j < 4; j++) oacc[nt][j] = 0.f;
    float m0 = -1e30f, m1 = -1e30f, l0 = 0.f, l1 = 0.f;

    int ntiles = (seqlen + 63) >> 6;
    const __half* kb = k + (size_t)(b*S)*C + head*HD;
    const __half* vb = v + (size_t)(b*S)*C + head*HD;

    for (int kt = 0; kt < ntiles; kt++) {
        __syncthreads();
        #pragma unroll
        for (int i = 0; i < 4; i++) {
            int idx = tid + i*256;
            int row = idx >> 4, g = idx & 15;
            size_t goff = (size_t)(kt*64 + row)*C + g*8;
            *(uint4*)&Ks[row*QK_ST + g*4] = *(const uint4*)(kb + goff);
            *(uint4*)&Vs[row*QK_ST + g*4] = *(const uint4*)(vb + goff);
        }
        __syncthreads();

        // S = Q K^T (raw scores; scale folded into exp2 below)
        float sacc[8][4];
        #pragma unroll
        for (int nt = 0; nt < 8; nt++)
            #pragma unroll
            for (int j = 0; j < 4; j++) sacc[nt][j] = 0.f;

        #pragma unroll
        for (int ks = 0; ks < 8; ks++) {
            unsigned a0, a1, a2, a3;
            ldmx4(a0, a1, a2, a3,
                  qsb + (uint32_t)(((qrow + lmr)*QK_ST + ks*8 + lmc)*4));
            #pragma unroll
            for (int ntp = 0; ntp < 4; ntp++) {
                unsigned b0, b1, b2, b3;
                ldmx4(b0, b1, b2, b3,
                      ksb + (uint32_t)(((ntp*16 + lmr)*QK_ST + ks*8 + lmc)*4));
                mma_f16(sacc[2*ntp  ], a0, a1, a2, a3, b0, b2);
                mma_f16(sacc[2*ntp+1], a0, a1, a2, a3, b1, b3);
            }
        }

        // mask (last partial tile only)
        if (kt*64 + 64 > seqlen) {
            #pragma unroll
            for (int nt = 0; nt < 8; nt++) {
                int c0 = kt*64 + nt*8 + 2*gc;
                if (c0     >= seqlen) { sacc[nt][0] = -1e30f; sacc[nt][2] = -1e30f; }
                if (c0 + 1 >= seqlen) { sacc[nt][1] = -1e30f; sacc[nt][3] = -1e30f; }
            }
        }

        // online softmax (fp32); rows gr (regs 0,1) and gr+8 (regs 2,3)
        float rm0 = -1e30f, rm1 = -1e30f;
        #pragma unroll
        for (int nt = 0; nt < 8; nt++) {
            rm0 = fmaxf(rm0, fmaxf(sacc[nt][0], sacc[nt][1]));
            rm1 = fmaxf(rm1, fmaxf(sacc[nt][2], sacc[nt][3]));
        }
        rm0 = fmaxf(rm0, __shfl_xor_sync(0xffffffffu, rm0, 1));
        rm0 = fmaxf(rm0, __shfl_xor_sync(0xffffffffu, rm0, 2));
        rm1 = fmaxf(rm1, __shfl_xor_sync(0xffffffffu, rm1, 1));
        rm1 = fmaxf(rm1, __shfl_xor_sync(0xffffffffu, rm1, 2));
        float mn0 = fmaxf(m0, rm0), mn1 = fmaxf(m1, rm1);
        float al0 = exp2f((m0 - mn0) * SCL2E);
        float al1 = exp2f((m1 - mn1) * SCL2E);
        #pragma unroll
        for (int nt = 0; nt < 16; nt++) {
            oacc[nt][0] *= al0; oacc[nt][1] *= al0;
            oacc[nt][2] *= al1; oacc[nt][3] *= al1;
        }
        float ps0 = 0.f, ps1 = 0.f;
        #pragma unroll
        for (int nt = 0; nt < 8; nt++) {
            float p0 = exp2f((sacc[nt][0] - mn0) * SCL2E);
            float p1 = exp2f((sacc[nt][1] - mn0) * SCL2E);
            float p2 = exp2f((sacc[nt][2] - mn1) * SCL2E);
            float p3 = exp2f((sacc[nt][3] - mn1) * SCL2E);
            ps0 += p0 + p1;
            ps1 += p2 + p3;
            Ps[(qrow+gr  )*PS_ST + nt*4 + gc] = packh2(p0, p1);
            Ps[(qrow+gr+8)*PS_ST + nt*4 + gc] = packh2(p2, p3);
        }
        ps0 += __shfl_xor_sync(0xffffffffu, ps0, 1);
        ps0 += __shfl_xor_sync(0xffffffffu, ps0, 2);
        ps1 += __shfl_xor_sync(0xffffffffu, ps1, 1);
        ps1 += __shfl_xor_sync(0xffffffffu, ps1, 2);
        l0 = l0*al0 + ps0; m0 = mn0;
        l1 = l1*al1 + ps1; m1 = mn1;
        __syncwarp();

        // O += P V  (4 k-steps of k16 over 64 keys)
        #pragma unroll
        for (int ks2 = 0; ks2 < 4; ks2++) {
            unsigned a0, a1, a2, a3;
            ldmx4(a0, a1, a2, a3,
                  psb + (uint32_t)(((qrow + lmr)*PS_ST + ks2*8 + lmc)*4));
            uint32_t va = vsb + (uint32_t)(((ks2*16 + vrow)*QK_ST + vcol4) * 4);
            #pragma unroll
            for (int ntp = 0; ntp < 8; ntp++) {
                unsigned m0r, m1r, m2r, m3r;
                ldmx4t(m0r, m1r, m2r, m3r, va + ntp*32);
                mma_f16(oacc[2*ntp  ], a0, a1, a2, a3, m0r, m1r);
                mma_f16(oacc[2*ntp+1], a0, a1, a2, a3, m2r, m3r);
            }
        }
        __syncwarp();
    }

    float inv0 = 1.0f / l0, inv1 = 1.0f / l1;
    __half* ob = out + (size_t)(b*S + qt*128 + qrow + gr)*C + head*HD;
    #pragma unroll
    for (int nt2 = 0; nt2 < 16; nt2++) {
        int col = nt2*8 + 2*gc;
        *(unsigned*)(ob + col) =
            packh2(oacc[nt2][0]*inv0, oacc[nt2][1]*inv0);
        *(unsigned*)(ob + (size_t)8*C + col) =
            packh2(oacc[nt2][2]*inv1, oacc[nt2][3]*inv1);
    }
}

// ---------------------------------------------------------------------------
extern "C" void kernel_launch(void* const* d_in, const int* in_sizes, int n_in,
                              void* d_out, int out_size)
{
    const float* x     = (const float*)d_in[0];
    const int*   seq   = (const int*)  d_in[1];
    const float* freqs = (const float*)d_in[3];
    const float* Wq    = (const float*)d_in[4];
    const float* bq    = (const float*)d_in[5];
    const float* Wk    = (const float*)d_in[6];
    const float* bk    = (const float*)d_in[7];
    const float* Wv    = (const float*)d_in[8];
    const float* bv    = (const float*)d_in[9];
    const float* Wo    = (const float*)d_in[10];
    const float* bo    = (const float*)d_in[11];
    const float* nqw   = (const float*)d_in[12];
    const float* nkw   = (const float*)d_in[13];
    float* out = (float*)d_out;

    float  *pq, *pk;
    __half *pxh, *pwh, *pqh, *pkh, *pvh, *poh;
    cudaGetSymbolAddress((void**)&pq,  g_q);
    cudaGetSymbolAddress((void**)&pk,  g_k);
    cudaGetSymbolAddress((void**)&pxh, g_xh);
    cudaGetSymbolAddress((void**)&pwh, g_wh);
    cudaGetSymbolAddress((void**)&pqh, g_qh);
    cudaGetSymbolAddress((void**)&pkh, g_kh);
    cudaGetSymbolAddress((void**)&pvh, g_vh);
    cudaGetSymbolAddress((void**)&poh, g_oh);

    cudaFuncSetAttribute(flash_f16,
                         cudaFuncAttributeMaxDynamicSharedMemorySize, FA_SMEM);

    // one-shot conversions (deterministic, every call)
    f2h<<<BS*C/1024, 256>>>(x,  pxh);
    f2h<<<CC/1024,   256>>>(Wq, pwh);
    f2h<<<CC/1024,   256>>>(Wk, pwh + CC);
    f2h<<<CC/1024,   256>>>(Wv, pwh + 2*CC);
    f2h<<<CC/1024,   256>>>(Wo, pwh + 3*CC);

    dim3 gg(C/128, BS/128);
    hgemm<false><<<gg, 256>>>(pxh, pwh,        bq, pq,  BS, C, C);
    hgemm<false><<<gg, 256>>>(pxh, pwh + CC,   bk, pk,  BS, C, C);
    hgemm<true ><<<gg, 256>>>(pxh, pwh + 2*CC, bv, pvh, BS, C, C);

    rmsnorm_rope<<<BS, 256>>>(pq, pqh, nqw, freqs);
    rmsnorm_rope<<<BS, 256>>>(pk, pkh, nkw, freqs);

    flash_f16<<<dim3(S/128, NH, B), 256, FA_SMEM>>>(pqh, pkh, pvh, seq, poh);

    hgemm<false><<<gg, 256>>>(poh, pwh + 3*CC, bo, out, BS, C, C);
}

// round 14
// speedup vs baseline: 7.3656x; 1.1230x over previous
#include <cuda_runtime.h>
#include <cuda_fp16.h>
#include <math.h>
#include <stdint.h>

#define B 2
#define S 3072
#define C 1536
#define NH 12
#define HD 128
#define BS (B*S)
#define CC (C*C)

// Scratch (allocation-free rule: device globals)
__device__ float  g_q [BS*C];          // Q projection, fp32 (pre-norm)
__device__ float  g_k [BS*C];          // K projection, fp32 (pre-norm)
__device__ __half g_xh[BS*C];          // x in fp16
__device__ __half g_wh[4*CC];          // Wq|Wk|Wv|Wo in fp16
__device__ __half g_qh[BS*C];          // Q normed+roped, fp16
__device__ __half g_kh[BS*C];          // K normed+roped, fp16
__device__ __half g_vh[BS*C];          // V, fp16
__device__ __half g_oh[BS*C];          // attention out, fp16

// ---------------------------------------------------------------------------
// helpers
// ---------------------------------------------------------------------------
__device__ __forceinline__ unsigned packh2(float x, float y) {
    __half2 h = __floats2half2_rn(x, y);
    return *reinterpret_cast<unsigned*>(&h);
}

__device__ __forceinline__ void mma_f16(float* d,
    unsigned a0, unsigned a1, unsigned a2, unsigned a3,
    unsigned b0, unsigned b1)
{
    asm volatile(
        "mma.sync.aligned.m16n8k16.row.col.f32.f16.f16.f32 "
        "{%0,%1,%2,%3}, {%4,%5,%6,%7}, {%8,%9}, {%0,%1,%2,%3};\n"
        : "+f"(d[0]), "+f"(d[1]), "+f"(d[2]), "+f"(d[3])
        : "r"(a0), "r"(a1), "r"(a2), "r"(a3), "r"(b0), "r"(b1));
}

__device__ __forceinline__ void ldmx4(unsigned& r0, unsigned& r1,
                                      unsigned& r2, unsigned& r3, uint32_t a)
{
    asm volatile(
        "ldmatrix.sync.aligned.m8n8.x4.shared.b16 {%0,%1,%2,%3}, [%4];"
        : "=r"(r0), "=r"(r1), "=r"(r2), "=r"(r3) : "r"(a));
}

__device__ __forceinline__ void ldmx4t(unsigned& r0, unsigned& r1,
                                       unsigned& r2, unsigned& r3, uint32_t a)
{
    asm volatile(
        "ldmatrix.sync.aligned.m8n8.x4.trans.shared.b16 {%0,%1,%2,%3}, [%4];"
        : "=r"(r0), "=r"(r1), "=r"(r2), "=r"(r3) : "r"(a));
}

__device__ __forceinline__ void cpa16(uint32_t dst, const void* src) {
    asm volatile("cp.async.cg.shared.global [%0], [%1], 16;"
                 :: "r"(dst), "l"(src) : "memory");
}
__device__ __forceinline__ void cpa_commit() {
    asm volatile("cp.async.commit_group;" ::: "memory");
}
__device__ __forceinline__ void cpa_wait0() {
    asm volatile("cp.async.wait_group 0;" ::: "memory");
}
__device__ __forceinline__ void cpa_wait1() {
    asm volatile("cp.async.wait_group 1;" ::: "memory");
}

// ---------------------------------------------------------------------------
// one-shot fp32 -> fp16 conversion
// ---------------------------------------------------------------------------
__global__ __launch_bounds__(256) void f2h(
    const float* __restrict__ s, __half* __restrict__ d)
{
    int i = blockIdx.x * 256 + threadIdx.x;
    float4 v = ((const float4*)s)[i];
    ((uint2*)d)[i] = make_uint2(packh2(v.x, v.y), packh2(v.z, v.w));
}

// ---------------------------------------------------------------------------
// fp16 GEMM: Cout[m][n] = sum_k A[m][k]*W[n][k] + bias[n]
// 128x128 tile, BK=32, 8 warps, warp tile 32x64.
// cp.async 3-stage pipeline: copies run 2 chunks ahead of compute.
// ---------------------------------------------------------------------------
#define GST 20
#define GBUF (128*GST)

template<bool HOUT>
__global__ __launch_bounds__(256) void hgemm(
    const __half* __restrict__ Ah, const __half* __restrict__ Wh,
    const float* __restrict__ bias, void* __restrict__ CoutV,
    int M, int N, int K)
{
    extern __shared__ unsigned gsm[];
    unsigned* As = gsm;             // 3*GBUF
    unsigned* Bs = gsm + 3*GBUF;    // 3*GBUF
    int tid  = threadIdx.x;
    int bm   = blockIdx.y*128, bn = blockIdx.x*128;
    int lr2  = tid >> 2, lc2 = tid & 3;    // staging: base row, 16B group
    int wid  = tid >> 5, lane = tid & 31;
    int wm   = wid & 3, wn = wid >> 2;
    int gr   = lane >> 2, gc = lane & 3;
    int lmr  = lane & 15, lmc = (lane >> 4) * 4;

    uint32_t asb = (uint32_t)__cvta_generic_to_shared(As);
    uint32_t bsb = (uint32_t)__cvta_generic_to_shared(Bs);

    const __half* Ap = Ah + (size_t)(bm + lr2) * K;
    const __half* Wp = Wh + (size_t)(bn + lr2) * K;

    float acc[2][8][4];
    #pragma unroll
    for (int mt = 0; mt < 2; mt++)
        #pragma unroll
        for (int nt = 0; nt < 8; nt++)
            #pragma unroll
            for (int j = 0; j < 4; j++) acc[mt][nt][j] = 0.f;

    const int nch = K / 32;   // 48

    auto stage = [&](int ch, int buf) {
        int k0 = ch * 32;
        uint32_t off = (uint32_t)((lr2*GST + lc2*4) * 4);
        uint32_t ab = asb + (uint32_t)buf * (GBUF*4) + off;
        uint32_t bb = bsb + (uint32_t)buf * (GBUF*4) + off;
        cpa16(ab,            Ap + k0 + lc2*8);
        cpa16(ab + 64*GST*4, Ap + (size_t)64*K + k0 + lc2*8);
        cpa16(bb,            Wp + k0 + lc2*8);
        cpa16(bb + 64*GST*4, Wp + (size_t)64*K + k0 + lc2*8);
        cpa_commit();
    };

    stage(0, 0);
    stage(1, 1);

    for (int ch = 0; ch < nch; ch++) {
        if (ch < nch - 1) cpa_wait1(); else cpa_wait0();
        __syncthreads();
        if (ch + 2 < nch) stage(ch + 2, (ch + 2) % 3);

        int buf = ch % 3;
        uint32_t ab = asb + (uint32_t)buf * (GBUF*4);
        uint32_t bb = bsb + (uint32_t)buf * (GBUF*4);
        #pragma unroll
        for (int ks = 0; ks < 2; ks++) {
            unsigned af[2][4];
            #pragma unroll
            for (int mt = 0; mt < 2; mt++)
                ldmx4(af[mt][0], af[mt][1], af[mt][2], af[mt][3],
                      ab + (uint32_t)(((wm*32 + mt*16 + lmr)*GST + ks*8 + lmc)*4));
            #pragma unroll
            for (int ntp = 0; ntp < 4; ntp++) {
                unsigned b0, b1, b2, b3;
                ldmx4(b0, b1, b2, b3,
                      bb + (uint32_t)(((wn*64 + ntp*16 + lmr)*GST + ks*8 + lmc)*4));
                mma_f16(acc[0][2*ntp  ], af[0][0],af[0][1],af[0][2],af[0][3], b0, b2);
                mma_f16(acc[0][2*ntp+1], af[0][0],af[0][1],af[0][2],af[0][3], b1, b3);
                mma_f16(acc[1][2*ntp  ], af[1][0],af[1][1],af[1][2],af[1][3], b0, b2);
                mma_f16(acc[1][2*ntp+1], af[1][0],af[1][1],af[1][2],af[1][3], b1, b3);
            }
        }
    }

    #pragma unroll
    for (int mt = 0; mt < 2; mt++) {
        int r0 = bm + wm*32 + mt*16 + gr;
        #pragma unroll
        for (int nt = 0; nt < 8; nt++) {
            int col = bn + wn*64 + nt*8 + 2*gc;
            float2 bb2 = *(const float2*)(bias + col);
            if (HOUT) {
                __half* Ch = (__half*)CoutV;
                *(unsigned*)&Ch[(size_t)r0*N + col] =
                    packh2(acc[mt][nt][0] + bb2.x, acc[mt][nt][1] + bb2.y);
                *(unsigned*)&Ch[(size_t)(r0+8)*N + col] =
                    packh2(acc[mt][nt][2] + bb2.x, acc[mt][nt][3] + bb2.y);
            } else {
                float* Cf = (float*)CoutV;
                *(float2*)&Cf[(size_t)r0*N + col] =
                    make_float2(acc[mt][nt][0] + bb2.x, acc[mt][nt][1] + bb2.y);
                *(float2*)&Cf[(size_t)(r0+8)*N + col] =
                    make_float2(acc[mt][nt][2] + bb2.x, acc[mt][nt][3] + bb2.y);
            }
        }
    }
}
#define HGEMM_SMEM (6*GBUF*4)

// ---------------------------------------------------------------------------
// Fused RMSNorm + RoPE: fp32 in, fp16 out (unchanged, proven)
// ---------------------------------------------------------------------------
__global__ __launch_bounds__(256) void rmsnorm_rope(
    const float* __restrict__ t, __half* __restrict__ dsth,
    const float* __restrict__ nw, const float* __restrict__ freqs)
{
    int bs = blockIdx.x;
    int s = bs % S;
    int tid = threadIdx.x;
    const float2* row = (const float2*)(t + (size_t)bs * C);
    unsigned* drow = (unsigned*)(dsth + (size_t)bs * C);
    const float2* wr = (const float2*)nw;

    float2 pv[3], pw[3];
    float ss = 0.f;
    #pragma unroll
    for (int i = 0; i < 3; i++) {
        pv[i] = row[tid + i*256];
        pw[i] = wr[tid + i*256];
        ss += pv[i].x*pv[i].x + pv[i].y*pv[i].y;
    }
    #pragma unroll
    for (int off = 16; off; off >>= 1)
        ss += __shfl_xor_sync(0xffffffffu, ss, off);

    __shared__ float red[8];
    __shared__ float cs[64], sn[64];
    if ((tid & 31) == 0) red[tid >> 5] = ss;
    __syncthreads();
    if (tid < 32) {
        float tsum = (tid < 8) ? red[tid] : 0.f;
        #pragma unroll
        for (int off = 4; off; off >>= 1)
            tsum += __shfl_xor_sync(0xffffffffu, tsum, off);
        if (tid == 0) red[0] = tsum;
    }
    if (tid >= 64 && tid < 128) {
        int j = tid - 64;
        int f = s / 768, r = s % 768, h = r / 32, w = r % 32;
        int sel = (j < 22) ? f : ((j < 43) ? h : w);
        float ang = freqs[sel*64 + j];
        cs[j] = cosf(ang);
        sn[j] = sinf(ang);
    }
    __syncthreads();

    float scale = rsqrtf(red[0] * (1.0f / C) + 1e-6f);
    #pragma unroll
    for (int i = 0; i < 3; i++) {
        int p = tid + i*256;
        int ci = p & 63;
        float e = pv[i].x * scale * pw[i].x;
        float o = pv[i].y * scale * pw[i].y;
        drow[p] = packh2(e*cs[ci] - o*sn[ci], e*sn[ci] + o*cs[ci]);
    }
}

// ---------------------------------------------------------------------------
// fp16 flash attention: BM=128 queries, BN=128 keys, d=128. fp16 in/out.
// Q fragments hoisted to registers; K/V double-buffered via cp.async;
// P goes straight from QK accumulators to PV A-fragments (no smem).
// ---------------------------------------------------------------------------
#define QK_ST 68
#define FTILE (128*QK_ST)        // 8704 uints = 34816 B per tile
#define FA_SMEM (5*FTILE*4)      // Qs + 2*Ks + 2*Vs = 174080 B

__global__ __launch_bounds__(256, 1) void flash_f16(
    const __half* __restrict__ q, const __half* __restrict__ k,
    const __half* __restrict__ v, const int* __restrict__ seq_lens,
    __half* __restrict__ out)
{
    extern __shared__ unsigned sm[];
    unsigned* Qs = sm;                 // FTILE
    // Ks: sm + FTILE + buf*FTILE ; Vs: sm + 3*FTILE + buf*FTILE

    int qt = blockIdx.x, head = blockIdx.y, b = blockIdx.z;
    int tid = threadIdx.x;
    int wid = tid >> 5, lane = tid & 31;
    int gr = lane >> 2, gc = lane & 3;
    int qrow = wid * 16;
    int seqlen = seq_lens[b];
    const float SCL2E = 0.08838834764831845f * 1.4426950408889634f;

    uint32_t qsb = (uint32_t)__cvta_generic_to_shared(Qs);
    uint32_t ksb = qsb + FTILE*4;
    uint32_t vsb = qsb + 3*FTILE*4;
    int lmr = lane & 15, lmc = (lane >> 4) * 4;
    int vrow = lane & 15, vcol4 = (lane >> 4) * 4;

    const __half* kb = k + (size_t)(b*S)*C + head*HD;
    const __half* vb = v + (size_t)(b*S)*C + head*HD;

    auto stageKV = [&](int kt, int buf) {
        uint32_t kd = ksb + (uint32_t)buf * (FTILE*4);
        uint32_t vd = vsb + (uint32_t)buf * (FTILE*4);
        #pragma unroll
        for (int i = 0; i < 8; i++) {
            int idx = tid + i*256;
            int row = idx >> 4, g = idx & 15;
            size_t goff = (size_t)(kt*128 + row)*C + g*8;
            uint32_t so = (uint32_t)((row*QK_ST + g*4) * 4);
            cpa16(kd + so, kb + goff);
            cpa16(vd + so, vb + goff);
        }
        cpa_commit();
    };

    // Stage Q (plain copy) + kick off tile 0 K/V
    const __half* qb = q + (size_t)(b*S + qt*128)*C + head*HD;
    #pragma unroll
    for (int i = 0; i < 8; i++) {
        int idx = tid + i*256;
        int row = idx >> 4, g = idx & 15;
        *(uint4*)&Qs[row*QK_ST + g*4] = *(const uint4*)(qb + (size_t)row*C + g*8);
    }
    stageKV(0, 0);
    __syncthreads();

    // Hoist Q fragments to registers (read Q smem once)
    unsigned qf[8][4];
    #pragma unroll
    for (int ks = 0; ks < 8; ks++)
        ldmx4(qf[ks][0], qf[ks][1], qf[ks][2], qf[ks][3],
              qsb + (uint32_t)(((qrow + lmr)*QK_ST + ks*8 + lmc)*4));

    float oacc[16][4];
    #pragma unroll
    for (int nt = 0; nt < 16; nt++)
        #pragma unroll
        for (int j = 0; j < 4; j++) oacc[nt][j] = 0.f;
    float m0 = -1e30f, m1 = -1e30f, l0 = 0.f, l1 = 0.f;

    int ntiles = (seqlen + 127) >> 7;

    for (int kt = 0; kt < ntiles; kt++) {
        cpa_wait0();
        __syncthreads();
        if (kt + 1 < ntiles) stageKV(kt + 1, (kt + 1) & 1);

        uint32_t kbase = ksb + (uint32_t)(kt & 1) * (FTILE*4);
        uint32_t vbase = vsb + (uint32_t)(kt & 1) * (FTILE*4);

        // S = Q K^T  (raw scores; scale folded into exp2)
        float sacc[16][4];
        #pragma unroll
        for (int nt = 0; nt < 16; nt++)
            #pragma unroll
            for (int j = 0; j < 4; j++) sacc[nt][j] = 0.f;

        #pragma unroll
        for (int ks = 0; ks < 8; ks++) {
            #pragma unroll
            for (int ntp = 0; ntp < 8; ntp++) {
                unsigned b0, b1, b2, b3;
                ldmx4(b0, b1, b2, b3,
                      kbase + (uint32_t)(((ntp*16 + lmr)*QK_ST + ks*8 + lmc)*4));
                mma_f16(sacc[2*ntp  ], qf[ks][0],qf[ks][1],qf[ks][2],qf[ks][3], b0, b2);
                mma_f16(sacc[2*ntp+1], qf[ks][0],qf[ks][1],qf[ks][2],qf[ks][3], b1, b3);
            }
        }

        // mask (last partial tile only)
        if (kt*128 + 128 > seqlen) {
            #pragma unroll
            for (int nt = 0; nt < 16; nt++) {
                int c0 = kt*128 + nt*8 + 2*gc;
                if (c0     >= seqlen) { sacc[nt][0] = -1e30f; sacc[nt][2] = -1e30f; }
                if (c0 + 1 >= seqlen) { sacc[nt][1] = -1e30f; sacc[nt][3] = -1e30f; }
            }
        }

        // online softmax (fp32); rows gr (regs 0,1) and gr+8 (regs 2,3)
        float rm0 = -1e30f, rm1 = -1e30f;
        #pragma unroll
        for (int nt = 0; nt < 16; nt++) {
            rm0 = fmaxf(rm0, fmaxf(sacc[nt][0], sacc[nt][1]));
            rm1 = fmaxf(rm1, fmaxf(sacc[nt][2], sacc[nt][3]));
        }
        rm0 = fmaxf(rm0, __shfl_xor_sync(0xffffffffu, rm0, 1));
        rm0 = fmaxf(rm0, __shfl_xor_sync(0xffffffffu, rm0, 2));
        rm1 = fmaxf(rm1, __shfl_xor_sync(0xffffffffu, rm1, 1));
        rm1 = fmaxf(rm1, __shfl_xor_sync(0xffffffffu, rm1, 2));
        float mn0 = fmaxf(m0, rm0), mn1 = fmaxf(m1, rm1);
        float al0 = exp2f((m0 - mn0) * SCL2E);
        float al1 = exp2f((m1 - mn1) * SCL2E);
        #pragma unroll
        for (int nt = 0; nt < 16; nt++) {
            oacc[nt][0] *= al0; oacc[nt][1] *= al0;
            oacc[nt][2] *= al1; oacc[nt][3] *= al1;
        }
        // exp + pack P directly into PV A-fragment registers
        unsigned ap[16][2];
        float ps0 = 0.f, ps1 = 0.f;
        #pragma unroll
        for (int nt = 0; nt < 16; nt++) {
            float p0 = exp2f((sacc[nt][0] - mn0) * SCL2E);
            float p1 = exp2f((sacc[nt][1] - mn0) * SCL2E);
            float p2 = exp2f((sacc[nt][2] - mn1) * SCL2E);
            float p3 = exp2f((sacc[nt][3] - mn1) * SCL2E);
            ps0 += p0 + p1;
            ps1 += p2 + p3;
            ap[nt][0] = packh2(p0, p1);
            ap[nt][1] = packh2(p2, p3);
        }
        ps0 += __shfl_xor_sync(0xffffffffu, ps0, 1);
        ps0 += __shfl_xor_sync(0xffffffffu, ps0, 2);
        ps1 += __shfl_xor_sync(0xffffffffu, ps1, 1);
        ps1 += __shfl_xor_sync(0xffffffffu, ps1, 2);
        l0 = l0*al0 + ps0; m0 = mn0;
        l1 = l1*al1 + ps1; m1 = mn1;

        // O += P V  (8 k-steps of k16 over 128 keys; A-frags from registers)
        #pragma unroll
        for (int ks2 = 0; ks2 < 8; ks2++) {
            unsigned a0 = ap[2*ks2  ][0], a1 = ap[2*ks2  ][1];
            unsigned a2 = ap[2*ks2+1][0], a3 = ap[2*ks2+1][1];
            uint32_t va = vbase + (uint32_t)(((ks2*16 + vrow)*QK_ST + vcol4) * 4);
            #pragma unroll
            for (int ntp = 0; ntp < 8; ntp++) {
                unsigned m0r, m1r, m2r, m3r;
                ldmx4t(m0r, m1r, m2r, m3r, va + ntp*32);
                mma_f16(oacc[2*ntp  ], a0, a1, a2, a3, m0r, m1r);
                mma_f16(oacc[2*ntp+1], a0, a1, a2, a3, m2r, m3r);
            }
        }
    }

    float inv0 = 1.0f / l0, inv1 = 1.0f / l1;
    __half* ob = out + (size_t)(b*S + qt*128 + qrow + gr)*C + head*HD;
    #pragma unroll
    for (int nt2 = 0; nt2 < 16; nt2++) {
        int col = nt2*8 + 2*gc;
        *(unsigned*)(ob + col) =
            packh2(oacc[nt2][0]*inv0, oacc[nt2][1]*inv0);
        *(unsigned*)(ob + (size_t)8*C + col) =
            packh2(oacc[nt2][2]*inv1, oacc[nt2][3]*inv1);
    }
}

// ---------------------------------------------------------------------------
extern "C" void kernel_launch(void* const* d_in, const int* in_sizes, int n_in,
                              void* d_out, int out_size)
{
    const float* x     = (const float*)d_in[0];
    const int*   seq   = (const int*)  d_in[1];
    const float* freqs = (const float*)d_in[3];
    const float* Wq    = (const float*)d_in[4];
    const float* bq    = (const float*)d_in[5];
    const float* Wk    = (const float*)d_in[6];
    const float* bk    = (const float*)d_in[7];
    const float* Wv    = (const float*)d_in[8];
    const float* bv    = (const float*)d_in[9];
    const float* Wo    = (const float*)d_in[10];
    const float* bo    = (const float*)d_in[11];
    const float* nqw   = (const float*)d_in[12];
    const float* nkw   = (const float*)d_in[13];
    float* out = (float*)d_out;

    float  *pq, *pk;
    __half *pxh, *pwh, *pqh, *pkh, *pvh, *poh;
    cudaGetSymbolAddress((void**)&pq,  g_q);
    cudaGetSymbolAddress((void**)&pk,  g_k);
    cudaGetSymbolAddress((void**)&pxh, g_xh);
    cudaGetSymbolAddress((void**)&pwh, g_wh);
    cudaGetSymbolAddress((void**)&pqh, g_qh);
    cudaGetSymbolAddress((void**)&pkh, g_kh);
    cudaGetSymbolAddress((void**)&pvh, g_vh);
    cudaGetSymbolAddress((void**)&poh, g_oh);

    cudaFuncSetAttribute(hgemm<false>,
                         cudaFuncAttributeMaxDynamicSharedMemorySize, HGEMM_SMEM);
    cudaFuncSetAttribute(hgemm<true>,
                         cudaFuncAttributeMaxDynamicSharedMemorySize, HGEMM_SMEM);
    cudaFuncSetAttribute(flash_f16,
                         cudaFuncAttributeMaxDynamicSharedMemorySize, FA_SMEM);

    // one-shot conversions (deterministic, every call)
    f2h<<<BS*C/1024, 256>>>(x,  pxh);
    f2h<<<CC/1024,   256>>>(Wq, pwh);
    f2h<<<CC/1024,   256>>>(Wk, pwh + CC);
    f2h<<<CC/1024,   256>>>(Wv, pwh + 2*CC);
    f2h<<<CC/1024,   256>>>(Wo, pwh + 3*CC);

    dim3 gg(C/128, BS/128);
    hgemm<false><<<gg, 256, HGEMM_SMEM>>>(pxh, pwh,        bq, pq,  BS, C, C);
    hgemm<false><<<gg, 256, HGEMM_SMEM>>>(pxh, pwh + CC,   bk, pk,  BS, C, C);
    hgemm<true ><<<gg, 256, HGEMM_SMEM>>>(pxh, pwh + 2*CC, bv, pvh, BS, C, C);

    rmsnorm_rope<<<BS, 256>>>(pq, pqh, nqw, freqs);
    rmsnorm_rope<<<BS, 256>>>(pk, pkh, nkw, freqs);

    flash_f16<<<dim3(S/128, NH, B), 256, FA_SMEM>>>(pqh, pkh, pvh, seq, poh);

    hgemm<false><<<gg, 256, HGEMM_SMEM>>>(poh, pwh + 3*CC, bo, out, BS, C, C);
}